// round 1
// baseline (speedup 1.0000x reference)
#include <cuda_runtime.h>

#define NB 4
#define DIMC 384
#define CC 64
#define GC 3
#define CIN 387
#define KPAD 400

// ---------------- scratch (device globals; no allocation allowed) ----------------
__device__ float d_s2[NB * DIMC * 28 * 28];
__device__ float d_s4[NB * DIMC * 56 * 56];
__device__ float d_s8[NB * DIMC * 112 * 112];
__device__ float d_s16[NB * DIMC * 224 * 224];
__device__ float d_gres[NB * GC * 112 * 112];
__device__ float d_comp[NB * CC * 112 * 112];
__device__ float d_maskb[NB * 36 * 112 * 112];
__device__ float d_wt[NB * 9 * 224 * 224];
__device__ float d_pwT[KPAD * DIMC];

// ---------------- packed f32x2 helpers (Blackwell FFMA2) ----------------
__device__ __forceinline__ unsigned long long ffma2(unsigned long long a,
                                                    unsigned long long b,
                                                    unsigned long long c) {
    unsigned long long d;
    asm("fma.rn.f32x2 %0, %1, %2, %3;" : "=l"(d) : "l"(a), "l"(b), "l"(c));
    return d;
}
__device__ __forceinline__ unsigned long long pack2(float lo, float hi) {
    unsigned long long d;
    asm("mov.b64 %0, {%1, %2};" : "=l"(d) : "f"(lo), "f"(hi));
    return d;
}
__device__ __forceinline__ unsigned long long dup2(float v) {
    unsigned long long d;
    asm("mov.b64 %0, {%1, %1};" : "=l"(d) : "f"(v));
    return d;
}
__device__ __forceinline__ float lo2(unsigned long long v) {
    return __uint_as_float((unsigned)(v & 0xffffffffull));
}
__device__ __forceinline__ float hi2(unsigned long long v) {
    return __uint_as_float((unsigned)(v >> 32));
}

// ---------------- bilinear resize matching jax.image.resize (antialias=True) ----------------
__global__ void resize_kernel(const float* __restrict__ g, float* __restrict__ out, int h) {
    int idx = blockIdx.x * blockDim.x + threadIdx.x;
    int total = NB * GC * h * h;
    if (idx >= total) return;
    int j = idx % h;
    int t = idx / h;
    int i = t % h;
    int bc = t / h;
    float scale = (float)h / 224.0f;   // out/in (<1 downsample)
    float inv = 224.0f / (float)h;     // kernel support radius
    float si = (i + 0.5f) * inv - 0.5f;
    float sj = (j + 0.5f) * inv - 0.5f;
    int i0 = max(0, (int)floorf(si - inv) + 1);
    int i1 = min(223, (int)ceilf(si + inv) - 1);
    int j0 = max(0, (int)floorf(sj - inv) + 1);
    int j1 = min(223, (int)ceilf(sj + inv) - 1);
    const float* gp = g + (size_t)bc * 224 * 224;
    float wj_sum = 0.f;
    for (int jj = j0; jj <= j1; ++jj)
        wj_sum += fmaxf(0.f, 1.f - fabsf((float)jj - sj) * scale);
    float wi_sum = 0.f, acc = 0.f;
    for (int ii = i0; ii <= i1; ++ii) {
        float wi = fmaxf(0.f, 1.f - fabsf((float)ii - si) * scale);
        wi_sum += wi;
        if (wi > 0.f) {
            float row = 0.f;
            const float* rp = gp + ii * 224;
            for (int jj = j0; jj <= j1; ++jj) {
                float wj = fmaxf(0.f, 1.f - fabsf((float)jj - sj) * scale);
                row += wj * rp[jj];
            }
            acc += wi * row;
        }
    }
    out[idx] = acc / (wi_sum * wj_sum);
}

// ---------------- comp: 1x1 conv 387 -> 64, f32x2 packed over output channels ----------------
// shared W layout: sW[c][o], o contiguous so (o, o+1) pairs load as b64.
__global__ void comp_kernel(const float* __restrict__ src, const float* __restrict__ gres,
                            const float* __restrict__ cw, const float* __restrict__ cb,
                            float* __restrict__ comp, int hw) {
    extern __shared__ float sW[]; // [CIN][CC]
    int tid = threadIdx.x;
    for (int i = tid; i < CIN * CC; i += blockDim.x) {
        int c = i >> 6, o = i & 63;
        sW[i] = cw[o * CIN + c];
    }
    __syncthreads();
    int pix = blockIdx.x * blockDim.x + tid;
    int b = blockIdx.y;
    if (pix >= hw) return;

    unsigned long long acc[32];
#pragma unroll
    for (int p = 0; p < 32; ++p)
        acc[p] = pack2(__ldg(&cb[2 * p]), __ldg(&cb[2 * p + 1]));

    const float* sp = src + (size_t)b * DIMC * hw + pix;
    for (int c = 0; c < DIMC; ++c) {
        float v = sp[(size_t)c * hw];
        unsigned long long vv = dup2(v);
        const ulonglong2* w2 = (const ulonglong2*)&sW[c * CC];
#pragma unroll
        for (int q = 0; q < 16; ++q) {
            ulonglong2 w = w2[q];
            acc[2 * q] = ffma2(vv, w.x, acc[2 * q]);
            acc[2 * q + 1] = ffma2(vv, w.y, acc[2 * q + 1]);
        }
    }
    const float* gp = gres + (size_t)b * GC * hw + pix;
#pragma unroll
    for (int c = 0; c < GC; ++c) {
        float v = gp[(size_t)c * hw];
        unsigned long long vv = dup2(v);
        const ulonglong2* w2 = (const ulonglong2*)&sW[(DIMC + c) * CC];
#pragma unroll
        for (int q = 0; q < 16; ++q) {
            ulonglong2 w = w2[q];
            acc[2 * q] = ffma2(vv, w.x, acc[2 * q]);
            acc[2 * q + 1] = ffma2(vv, w.y, acc[2 * q + 1]);
        }
    }
    float* op = comp + (size_t)b * CC * hw + pix;
#pragma unroll
    for (int p = 0; p < 32; ++p) {
        op[(size_t)(2 * p) * hw] = lo2(acc[p]);
        op[(size_t)(2 * p + 1) * hw] = hi2(acc[p]);
    }
}

// ---------------- mask: 3x3 conv 64 -> 36, pad 1, f32x2 packed over output channels ----------------
// shared E layout: sE[c][k][m], m contiguous.
__global__ void mask_kernel(const float* __restrict__ comp, const float* __restrict__ ew,
                            const float* __restrict__ eb, float* __restrict__ maskb, int h) {
    extern __shared__ float sE[]; // [CC][9][36]
    int tid = threadIdx.x;
    for (int i = tid; i < CC * 9 * 36; i += blockDim.x) {
        int m = i % 36;
        int ck = i / 36;
        int k = ck % 9;
        int c = ck / 9;
        sE[i] = ew[(m * CC + c) * 9 + k];
    }
    __syncthreads();
    int hw = h * h;
    int pix = blockIdx.x * blockDim.x + tid;
    int b = blockIdx.y;
    if (pix >= hw) return;
    int i = pix / h, j = pix % h;

    unsigned long long acc[18];
#pragma unroll
    for (int p = 0; p < 18; ++p)
        acc[p] = pack2(__ldg(&eb[2 * p]), __ldg(&eb[2 * p + 1]));

    int offs[9];
    bool val[9];
#pragma unroll
    for (int k = 0; k < 9; ++k) {
        int di = k / 3 - 1, dj = k % 3 - 1;
        int ii = i + di, jj = j + dj;
        val[k] = (ii >= 0) && (ii < h) && (jj >= 0) && (jj < h);
        offs[k] = ii * h + jj;
    }
    const float* cp = comp + (size_t)b * CC * hw;
    for (int c = 0; c < CC; ++c) {
        const float* cpc = cp + (size_t)c * hw;
#pragma unroll
        for (int k = 0; k < 9; ++k) {
            float v = val[k] ? cpc[offs[k]] : 0.f;
            unsigned long long vv = dup2(v);
            const ulonglong2* w2 = (const ulonglong2*)&sE[(c * 9 + k) * 36];
#pragma unroll
            for (int q = 0; q < 9; ++q) {
                ulonglong2 w = w2[q];
                acc[2 * q] = ffma2(vv, w.x, acc[2 * q]);
                acc[2 * q + 1] = ffma2(vv, w.y, acc[2 * q + 1]);
            }
        }
    }
    float* mp = maskb + (size_t)b * 36 * hw + pix;
#pragma unroll
    for (int p = 0; p < 18; ++p) {
        mp[(size_t)(2 * p) * hw] = lo2(acc[p]);
        mp[(size_t)(2 * p + 1) * hw] = hi2(acc[p]);
    }
}

// ---------------- pixel-shuffle + softmax over the 9 reassembly weights ----------------
__global__ void softmax_shuffle_kernel(const float* __restrict__ maskb,
                                       float* __restrict__ wt, int h) {
    int H = 2 * h;
    int HW = H * H, hw = h * h;
    int idx = blockIdx.x * blockDim.x + threadIdx.x;
    if (idx >= NB * HW) return;
    int J = idx % H;
    int t = idx / H;
    int I = t % H;
    int b = t / H;
    int i = I >> 1, p = I & 1, j = J >> 1, q = J & 1;
    const float* mp = maskb + ((size_t)b * 36 + (p * 2 + q)) * hw + i * h + j;
    float m[9], mx = -1e30f;
#pragma unroll
    for (int k = 0; k < 9; ++k) {
        m[k] = mp[(size_t)(k * 4) * hw];
        mx = fmaxf(mx, m[k]);
    }
    float s = 0.f;
#pragma unroll
    for (int k = 0; k < 9; ++k) {
        m[k] = __expf(m[k] - mx);
        s += m[k];
    }
    float inv = 1.f / s;
    float* wp = wt + (size_t)b * 9 * HW + I * H + J;
#pragma unroll
    for (int k = 0; k < 9; ++k) wp[(size_t)k * HW] = m[k] * inv;
}

// ---------------- CARAFE reassembly (SMEM-tiled input, weights in registers) ----------------
#define CARAFE_CH 4
__global__ __launch_bounds__(256) void carafe_kernel(const float* __restrict__ src,
                                                     const float* __restrict__ wt,
                                                     float* __restrict__ out, int h) {
    int H = 2 * h, hw = h * h, HW = H * H;
    int b = blockIdx.z;
    int I0 = blockIdx.y * 16;
    int J0 = blockIdx.x * 32;
    int tid = threadIdx.x;
    int tx = tid & 15, ty = tid >> 4;
    __shared__ float xs[CARAFE_CH][10][18];

    int I = I0 + ty;
    int J1 = J0 + tx, J2 = J0 + tx + 16;
    bool v1 = (I < H) && (J1 < H);
    bool v2 = (I < H) && (J2 < H);
    float w1[9], w2[9];
    const float* wb = wt + (size_t)b * 9 * HW;
#pragma unroll
    for (int k = 0; k < 9; ++k) {
        w1[k] = v1 ? wb[(size_t)k * HW + I * H + J1] : 0.f;
        w2[k] = v2 ? wb[(size_t)k * HW + I * H + J2] : 0.f;
    }
    int i0 = I0 >> 1, j0 = J0 >> 1;
    int li = (ty >> 1) + 1;
    int lj1 = (tx >> 1) + 1;
    int lj2 = ((tx + 16) >> 1) + 1;
    const float* sb = src + (size_t)b * DIMC * hw;
    float* ob = out + (size_t)b * DIMC * HW;

    for (int cc = 0; cc < DIMC; cc += CARAFE_CH) {
        for (int e = tid; e < CARAFE_CH * 180; e += 256) {
            int c = e / 180;
            int r = e % 180;
            int ii = r / 18, jj = r % 18;
            int gi = i0 - 1 + ii, gj = j0 - 1 + jj;
            float v = 0.f;
            if (gi >= 0 && gi < h && gj >= 0 && gj < h)
                v = sb[(size_t)(cc + c) * hw + gi * h + gj];
            xs[c][ii][jj] = v;
        }
        __syncthreads();
#pragma unroll
        for (int c = 0; c < CARAFE_CH; ++c) {
            float a1 = 0.f, a2 = 0.f;
#pragma unroll
            for (int k = 0; k < 9; ++k) {
                int di = k / 3, dj = k % 3;
                a1 += w1[k] * xs[c][li - 1 + di][lj1 - 1 + dj];
                a2 += w2[k] * xs[c][li - 1 + di][lj2 - 1 + dj];
            }
            if (v1) ob[(size_t)(cc + c) * HW + I * H + J1] = a1;
            if (v2) ob[(size_t)(cc + c) * HW + I * H + J2] = a2;
        }
        __syncthreads();
    }
}

// ---------------- transpose + zero-pad proj weights: pwT[c][o], c in [0,400) ----------------
__global__ void transpose_w_kernel(const float* __restrict__ pw, float* __restrict__ pwT) {
    int idx = blockIdx.x * blockDim.x + threadIdx.x;
    if (idx >= KPAD * DIMC) return;
    int o = idx % DIMC, c = idx / DIMC;
    pwT[idx] = (c < CIN) ? pw[o * CIN + c] : 0.f;
}

// ---------------- final 1x1 conv = GEMM [384x387]x[387x50176] per batch, FFMA2 ----------------
// BM=128, BN=128, BK=16, 256 threads, 8x8 microtile held as f32x2 pairs over M.
// B tile stored duplicated (each pixel value twice) so the {v,v} FFMA2 operand
// comes straight from shared with zero per-iteration MOVs.
__global__ __launch_bounds__(256) void proj_kernel(const float* __restrict__ s16,
                                                   const float* __restrict__ guid,
                                                   const float* __restrict__ pwT,
                                                   const float* __restrict__ pb,
                                                   float* __restrict__ out) {
    __shared__ float As[16][128];
    __shared__ float Bsd[16][256];
    const int tid = threadIdx.x;
    const int tx = tid & 15, ty = tid >> 4;
    const int b = blockIdx.z;
    const int o0 = blockIdx.y * 128;
    const int p0 = blockIdx.x * 128;
    const size_t NPIX = 50176;

    unsigned long long acc[4][8];
#pragma unroll
    for (int m = 0; m < 4; ++m)
#pragma unroll
        for (int n = 0; n < 8; ++n) acc[m][n] = 0ull;

    for (int kc = 0; kc < KPAD; kc += 16) {
        // A: 16 x 128 from transposed weights (fully coalesced float4)
        {
            int kk = tid >> 4;
            int o = (tid & 15) * 8;
            const float4* s4p = (const float4*)(pwT + (size_t)(kc + kk) * DIMC + o0 + o);
            *(float4*)&As[kk][o] = s4p[0];
            *(float4*)&As[kk][o + 4] = s4p[1];
        }
        // B: 16 x 128 pixels, stored duplicated
#pragma unroll
        for (int rep = 0; rep < 2; ++rep) {
            int f = tid + rep * 256;
            int kk = f >> 5;
            int col = (f & 31) * 4;
            int c = kc + kk;
            float4 v = make_float4(0.f, 0.f, 0.f, 0.f);
            if (c < DIMC)
                v = *(const float4*)(s16 + (size_t)(b * DIMC + c) * NPIX + p0 + col);
            else if (c < CIN)
                v = *(const float4*)(guid + (size_t)(b * GC + (c - DIMC)) * NPIX + p0 + col);
            *(float4*)&Bsd[kk][col * 2] = make_float4(v.x, v.x, v.y, v.y);
            *(float4*)&Bsd[kk][col * 2 + 4] = make_float4(v.z, v.z, v.w, v.w);
        }
        __syncthreads();
#pragma unroll
        for (int kk = 0; kk < 16; ++kk) {
            ulonglong2 a01 = *(const ulonglong2*)&As[kk][ty * 8];
            ulonglong2 a23 = *(const ulonglong2*)&As[kk][ty * 8 + 4];
            ulonglong2 b01 = *(const ulonglong2*)&Bsd[kk][tx * 16];
            ulonglong2 b23 = *(const ulonglong2*)&Bsd[kk][tx * 16 + 4];
            ulonglong2 b45 = *(const ulonglong2*)&Bsd[kk][tx * 16 + 8];
            ulonglong2 b67 = *(const ulonglong2*)&Bsd[kk][tx * 16 + 12];
            unsigned long long av[4] = {a01.x, a01.y, a23.x, a23.y};
            unsigned long long bv[8] = {b01.x, b01.y, b23.x, b23.y,
                                        b45.x, b45.y, b67.x, b67.y};
#pragma unroll
            for (int m = 0; m < 4; ++m)
#pragma unroll
                for (int n = 0; n < 8; ++n)
                    acc[m][n] = ffma2(av[m], bv[n], acc[m][n]);
        }
        __syncthreads();
    }
    // epilogue: each acc pair = output rows (2mp, 2mp+1)
#pragma unroll
    for (int mp = 0; mp < 4; ++mp) {
        int r0 = o0 + ty * 8 + mp * 2;
        float bias0 = __ldg(&pb[r0]);
        float bias1 = __ldg(&pb[r0 + 1]);
        float lo[8], hi[8];
#pragma unroll
        for (int n = 0; n < 8; ++n) {
            lo[n] = lo2(acc[mp][n]) + bias0;
            hi[n] = hi2(acc[mp][n]) + bias1;
        }
        float* o_r0 = out + (size_t)(b * DIMC + r0) * NPIX + p0 + tx * 8;
        float* o_r1 = o_r0 + NPIX;
        *(float4*)o_r0 = make_float4(lo[0], lo[1], lo[2], lo[3]);
        *(float4*)(o_r0 + 4) = make_float4(lo[4], lo[5], lo[6], lo[7]);
        *(float4*)o_r1 = make_float4(hi[0], hi[1], hi[2], hi[3]);
        *(float4*)(o_r1 + 4) = make_float4(hi[4], hi[5], hi[6], hi[7]);
    }
}

// ---------------- driver ----------------
extern "C" void kernel_launch(void* const* d_in, const int* in_sizes, int n_in,
                              void* d_out, int out_size) {
    (void)in_sizes; (void)n_in; (void)out_size;
    const float* source = (const float*)d_in[0];
    const float* guid = (const float*)d_in[1];
    const float* proj_w = (const float*)d_in[18];
    const float* proj_b = (const float*)d_in[19];

    float *s2, *s4, *s8, *s16, *gres, *comp, *maskb, *wtb, *pwT;
    cudaGetSymbolAddress((void**)&s2, d_s2);
    cudaGetSymbolAddress((void**)&s4, d_s4);
    cudaGetSymbolAddress((void**)&s8, d_s8);
    cudaGetSymbolAddress((void**)&s16, d_s16);
    cudaGetSymbolAddress((void**)&gres, d_gres);
    cudaGetSymbolAddress((void**)&comp, d_comp);
    cudaGetSymbolAddress((void**)&maskb, d_maskb);
    cudaGetSymbolAddress((void**)&wtb, d_wt);
    cudaGetSymbolAddress((void**)&pwT, d_pwT);

    cudaFuncSetAttribute(comp_kernel, cudaFuncAttributeMaxDynamicSharedMemorySize,
                         CIN * CC * 4);
    cudaFuncSetAttribute(mask_kernel, cudaFuncAttributeMaxDynamicSharedMemorySize,
                         CC * 9 * 36 * 4);

    const float* cur = source;
    float* outs[4] = {s2, s4, s8, s16};
    const int hs[4] = {14, 28, 56, 112};
    for (int s = 0; s < 4; ++s) {
        int h = hs[s], hw = h * h, H = 2 * h, HW = H * H;
        const float* cw = (const float*)d_in[2 + 4 * s];
        const float* cb = (const float*)d_in[3 + 4 * s];
        const float* ew = (const float*)d_in[4 + 4 * s];
        const float* eb = (const float*)d_in[5 + 4 * s];
        resize_kernel<<<(NB * GC * hw + 255) / 256, 256>>>(guid, gres, h);
        comp_kernel<<<dim3((hw + 127) / 128, NB), 128, CIN * CC * 4>>>(cur, gres, cw, cb,
                                                                       comp, hw);
        mask_kernel<<<dim3((hw + 127) / 128, NB), 128, CC * 9 * 36 * 4>>>(comp, ew, eb,
                                                                          maskb, h);
        softmax_shuffle_kernel<<<(NB * HW + 255) / 256, 256>>>(maskb, wtb, h);
        carafe_kernel<<<dim3((H + 31) / 32, (H + 15) / 16, NB), 256>>>(cur, wtb, outs[s], h);
        cur = outs[s];
    }
    transpose_w_kernel<<<(KPAD * DIMC + 255) / 256, 256>>>(proj_w, pwT);
    proj_kernel<<<dim3(392, 3, NB), 256>>>(s16, guid, pwT, proj_b, (float*)d_out);
}

// round 4
// speedup vs baseline: 1.8326x; 1.8326x over previous
#include <cuda_runtime.h>

#define NB 4
#define DIMC 384
#define CC 64
#define GC 3
#define CIN 387
#define KPAD 400

// ---------------- scratch (device globals; no allocation allowed) ----------------
__device__ float d_s2[NB * DIMC * 28 * 28];
__device__ float d_s4[NB * DIMC * 56 * 56];
__device__ float d_s8[NB * DIMC * 112 * 112];
__device__ float d_s16[NB * DIMC * 224 * 224];
__device__ float d_gres[NB * GC * 112 * 112];
__device__ float d_comp[NB * CC * 112 * 112];
__device__ float d_maskb[NB * 36 * 112 * 112];
__device__ float d_wt[NB * 9 * 224 * 224];
__device__ float d_pwT[KPAD * DIMC];

// ---------------- packed f32x2 helpers (Blackwell FFMA2) ----------------
__device__ __forceinline__ unsigned long long ffma2(unsigned long long a,
                                                    unsigned long long b,
                                                    unsigned long long c) {
    unsigned long long d;
    asm("fma.rn.f32x2 %0, %1, %2, %3;" : "=l"(d) : "l"(a), "l"(b), "l"(c));
    return d;
}
__device__ __forceinline__ unsigned long long pack2(float lo, float hi) {
    unsigned long long d;
    asm("mov.b64 %0, {%1, %2};" : "=l"(d) : "f"(lo), "f"(hi));
    return d;
}
__device__ __forceinline__ unsigned long long dup2(float v) {
    unsigned long long d;
    asm("mov.b64 %0, {%1, %1};" : "=l"(d) : "f"(v));
    return d;
}
__device__ __forceinline__ float lo2(unsigned long long v) {
    return __uint_as_float((unsigned)(v & 0xffffffffull));
}
__device__ __forceinline__ float hi2(unsigned long long v) {
    return __uint_as_float((unsigned)(v >> 32));
}

// ---------------- cp.async helpers ----------------
__device__ __forceinline__ unsigned smem_u32(const void* p) {
    unsigned a;
    asm("{ .reg .u64 t; cvta.to.shared.u64 t, %1; cvt.u32.u64 %0, t; }"
        : "=r"(a) : "l"(p));
    return a;
}
__device__ __forceinline__ void cpasync16(unsigned dst, const void* src, int srcbytes) {
    asm volatile("cp.async.ca.shared.global [%0], [%1], 16, %2;"
                 :: "r"(dst), "l"(src), "r"(srcbytes));
}
__device__ __forceinline__ void cp_commit() {
    asm volatile("cp.async.commit_group;");
}
template <int N>
__device__ __forceinline__ void cp_wait() {
    asm volatile("cp.async.wait_group %0;" :: "n"(N));
}

// ---------------- bilinear resize matching jax.image.resize (antialias=True) ----------------
__global__ void resize_kernel(const float* __restrict__ g, float* __restrict__ out, int h) {
    int idx = blockIdx.x * blockDim.x + threadIdx.x;
    int total = NB * GC * h * h;
    if (idx >= total) return;
    int j = idx % h;
    int t = idx / h;
    int i = t % h;
    int bc = t / h;
    float scale = (float)h / 224.0f;   // out/in (<1 downsample)
    float inv = 224.0f / (float)h;     // kernel support radius
    float si = (i + 0.5f) * inv - 0.5f;
    float sj = (j + 0.5f) * inv - 0.5f;
    int i0 = max(0, (int)floorf(si - inv) + 1);
    int i1 = min(223, (int)ceilf(si + inv) - 1);
    int j0 = max(0, (int)floorf(sj - inv) + 1);
    int j1 = min(223, (int)ceilf(sj + inv) - 1);
    const float* gp = g + (size_t)bc * 224 * 224;
    float wj_sum = 0.f;
    for (int jj = j0; jj <= j1; ++jj)
        wj_sum += fmaxf(0.f, 1.f - fabsf((float)jj - sj) * scale);
    float wi_sum = 0.f, acc = 0.f;
    for (int ii = i0; ii <= i1; ++ii) {
        float wi = fmaxf(0.f, 1.f - fabsf((float)ii - si) * scale);
        wi_sum += wi;
        if (wi > 0.f) {
            float row = 0.f;
            const float* rp = gp + ii * 224;
            for (int jj = j0; jj <= j1; ++jj) {
                float wj = fmaxf(0.f, 1.f - fabsf((float)jj - sj) * scale);
                row += wj * rp[jj];
            }
            acc += wi * row;
        }
    }
    out[idx] = acc / (wi_sum * wj_sum);
}

// ---------------- comp: 1x1 conv 387 -> 64, f32x2 packed over output channels ----------------
__global__ void comp_kernel(const float* __restrict__ src, const float* __restrict__ gres,
                            const float* __restrict__ cw, const float* __restrict__ cb,
                            float* __restrict__ comp, int hw) {
    extern __shared__ float sW[]; // [CIN][CC]
    int tid = threadIdx.x;
    for (int i = tid; i < CIN * CC; i += blockDim.x) {
        int c = i >> 6, o = i & 63;
        sW[i] = cw[o * CIN + c];
    }
    __syncthreads();
    int pix = blockIdx.x * blockDim.x + tid;
    int b = blockIdx.y;
    if (pix >= hw) return;

    unsigned long long acc[32];
#pragma unroll
    for (int p = 0; p < 32; ++p)
        acc[p] = pack2(__ldg(&cb[2 * p]), __ldg(&cb[2 * p + 1]));

    const float* sp = src + (size_t)b * DIMC * hw + pix;
    for (int c = 0; c < DIMC; ++c) {
        float v = sp[(size_t)c * hw];
        unsigned long long vv = dup2(v);
        const ulonglong2* w2 = (const ulonglong2*)&sW[c * CC];
#pragma unroll
        for (int q = 0; q < 16; ++q) {
            ulonglong2 w = w2[q];
            acc[2 * q] = ffma2(vv, w.x, acc[2 * q]);
            acc[2 * q + 1] = ffma2(vv, w.y, acc[2 * q + 1]);
        }
    }
    const float* gp = gres + (size_t)b * GC * hw + pix;
#pragma unroll
    for (int c = 0; c < GC; ++c) {
        float v = gp[(size_t)c * hw];
        unsigned long long vv = dup2(v);
        const ulonglong2* w2 = (const ulonglong2*)&sW[(DIMC + c) * CC];
#pragma unroll
        for (int q = 0; q < 16; ++q) {
            ulonglong2 w = w2[q];
            acc[2 * q] = ffma2(vv, w.x, acc[2 * q]);
            acc[2 * q + 1] = ffma2(vv, w.y, acc[2 * q + 1]);
        }
    }
    float* op = comp + (size_t)b * CC * hw + pix;
#pragma unroll
    for (int p = 0; p < 32; ++p) {
        op[(size_t)(2 * p) * hw] = lo2(acc[p]);
        op[(size_t)(2 * p + 1) * hw] = hi2(acc[p]);
    }
}

// ---------------- mask: 3x3 conv 64 -> 36, pad 1, f32x2 packed over output channels ----------------
__global__ void mask_kernel(const float* __restrict__ comp, const float* __restrict__ ew,
                            const float* __restrict__ eb, float* __restrict__ maskb, int h) {
    extern __shared__ float sE[]; // [CC][9][36]
    int tid = threadIdx.x;
    for (int i = tid; i < CC * 9 * 36; i += blockDim.x) {
        int m = i % 36;
        int ck = i / 36;
        int k = ck % 9;
        int c = ck / 9;
        sE[i] = ew[(m * CC + c) * 9 + k];
    }
    __syncthreads();
    int hw = h * h;
    int pix = blockIdx.x * blockDim.x + tid;
    int b = blockIdx.y;
    if (pix >= hw) return;
    int i = pix / h, j = pix % h;

    unsigned long long acc[18];
#pragma unroll
    for (int p = 0; p < 18; ++p)
        acc[p] = pack2(__ldg(&eb[2 * p]), __ldg(&eb[2 * p + 1]));

    int offs[9];
    bool val[9];
#pragma unroll
    for (int k = 0; k < 9; ++k) {
        int di = k / 3 - 1, dj = k % 3 - 1;
        int ii = i + di, jj = j + dj;
        val[k] = (ii >= 0) && (ii < h) && (jj >= 0) && (jj < h);
        offs[k] = ii * h + jj;
    }
    const float* cp = comp + (size_t)b * CC * hw;
    for (int c = 0; c < CC; ++c) {
        const float* cpc = cp + (size_t)c * hw;
#pragma unroll
        for (int k = 0; k < 9; ++k) {
            float v = val[k] ? cpc[offs[k]] : 0.f;
            unsigned long long vv = dup2(v);
            const ulonglong2* w2 = (const ulonglong2*)&sE[(c * 9 + k) * 36];
#pragma unroll
            for (int q = 0; q < 9; ++q) {
                ulonglong2 w = w2[q];
                acc[2 * q] = ffma2(vv, w.x, acc[2 * q]);
                acc[2 * q + 1] = ffma2(vv, w.y, acc[2 * q + 1]);
            }
        }
    }
    float* mp = maskb + (size_t)b * 36 * hw + pix;
#pragma unroll
    for (int p = 0; p < 18; ++p) {
        mp[(size_t)(2 * p) * hw] = lo2(acc[p]);
        mp[(size_t)(2 * p + 1) * hw] = hi2(acc[p]);
    }
}

// ---------------- pixel-shuffle + softmax over the 9 reassembly weights ----------------
__global__ void softmax_shuffle_kernel(const float* __restrict__ maskb,
                                       float* __restrict__ wt, int h) {
    int H = 2 * h;
    int HW = H * H, hw = h * h;
    int idx = blockIdx.x * blockDim.x + threadIdx.x;
    if (idx >= NB * HW) return;
    int J = idx % H;
    int t = idx / H;
    int I = t % H;
    int b = t / H;
    int i = I >> 1, p = I & 1, j = J >> 1, q = J & 1;
    const float* mp = maskb + ((size_t)b * 36 + (p * 2 + q)) * hw + i * h + j;
    float m[9], mx = -1e30f;
#pragma unroll
    for (int k = 0; k < 9; ++k) {
        m[k] = mp[(size_t)(k * 4) * hw];
        mx = fmaxf(mx, m[k]);
    }
    float s = 0.f;
#pragma unroll
    for (int k = 0; k < 9; ++k) {
        m[k] = __expf(m[k] - mx);
        s += m[k];
    }
    float inv = 1.f / s;
    float* wp = wt + (size_t)b * 9 * HW + I * H + J;
#pragma unroll
    for (int k = 0; k < 9; ++k) wp[(size_t)k * HW] = m[k] * inv;
}

// ---------------- CARAFE reassembly (SMEM-tiled input, weights in registers) ----------------
#define CARAFE_CH 8
__global__ __launch_bounds__(256) void carafe_kernel(const float* __restrict__ src,
                                                     const float* __restrict__ wt,
                                                     float* __restrict__ out, int h) {
    int H = 2 * h, hw = h * h, HW = H * H;
    int b = blockIdx.z;
    int I0 = blockIdx.y * 16;
    int J0 = blockIdx.x * 32;
    int tid = threadIdx.x;
    int tx = tid & 15, ty = tid >> 4;
    __shared__ float xs[CARAFE_CH][10][18];

    int I = I0 + ty;
    int J1 = J0 + tx, J2 = J0 + tx + 16;
    bool v1 = (I < H) && (J1 < H);
    bool v2 = (I < H) && (J2 < H);
    float w1[9], w2[9];
    const float* wb = wt + (size_t)b * 9 * HW;
#pragma unroll
    for (int k = 0; k < 9; ++k) {
        w1[k] = v1 ? wb[(size_t)k * HW + I * H + J1] : 0.f;
        w2[k] = v2 ? wb[(size_t)k * HW + I * H + J2] : 0.f;
    }
    int i0 = I0 >> 1, j0 = J0 >> 1;
    int li = (ty >> 1) + 1;
    int lj1 = (tx >> 1) + 1;
    int lj2 = ((tx + 16) >> 1) + 1;
    const float* sb = src + (size_t)b * DIMC * hw;
    float* ob = out + (size_t)b * DIMC * HW;

    for (int cc = 0; cc < DIMC; cc += CARAFE_CH) {
        for (int e = tid; e < CARAFE_CH * 180; e += 256) {
            int c = e / 180;
            int r = e % 180;
            int ii = r / 18, jj = r % 18;
            int gi = i0 - 1 + ii, gj = j0 - 1 + jj;
            float v = 0.f;
            if (gi >= 0 && gi < h && gj >= 0 && gj < h)
                v = sb[(size_t)(cc + c) * hw + gi * h + gj];
            xs[c][ii][jj] = v;
        }
        __syncthreads();
#pragma unroll
        for (int c = 0; c < CARAFE_CH; ++c) {
            float a1 = 0.f, a2 = 0.f;
#pragma unroll
            for (int k = 0; k < 9; ++k) {
                int di = k / 3, dj = k % 3;
                a1 += w1[k] * xs[c][li - 1 + di][lj1 - 1 + dj];
                a2 += w2[k] * xs[c][li - 1 + di][lj2 - 1 + dj];
            }
            if (v1) ob[(size_t)(cc + c) * HW + I * H + J1] = a1;
            if (v2) ob[(size_t)(cc + c) * HW + I * H + J2] = a2;
        }
        __syncthreads();
    }
}

// ---------------- transpose + zero-pad proj weights: pwT[c][o], c in [0,400) ----------------
__global__ void transpose_w_kernel(const float* __restrict__ pw, float* __restrict__ pwT) {
    int idx = blockIdx.x * blockDim.x + threadIdx.x;
    if (idx >= KPAD * DIMC) return;
    int o = idx % DIMC, c = idx / DIMC;
    pwT[idx] = (c < CIN) ? pw[o * CIN + c] : 0.f;
}

// ---------------- final 1x1 conv = GEMM [384x387]x[387x50176] per batch, FFMA2 ----------------
// BM=128, BN=128, BK=16, 256 threads, 8x8 microtile as 4 M-pairs x 8 N.
// No duplicated B in shared (dup happens in registers on the ALU pipe).
// cp.async double-buffered K tiles; forced 2 blocks/SM.
#define NKT (KPAD / 16)
__global__ __launch_bounds__(256, 2) void proj_kernel(const float* __restrict__ s16,
                                                      const float* __restrict__ guid,
                                                      const float* __restrict__ pwT,
                                                      const float* __restrict__ pb,
                                                      float* __restrict__ out) {
    __shared__ float As[2][16][128];
    __shared__ float Bs[2][16][128];
    const int tid = threadIdx.x;
    const int tx = tid & 15, ty = tid >> 4;
    const int b = blockIdx.z;
    const int o0 = blockIdx.y * 128;
    const int p0 = blockIdx.x * 128;
    const size_t NPIX = 50176;

    unsigned long long acc[4][8];
#pragma unroll
    for (int m = 0; m < 4; ++m)
#pragma unroll
        for (int n = 0; n < 8; ++n) acc[m][n] = 0ull;

    // tile loader: 512 float4 per tile for A and for B; 256 threads x 2 each
    auto load_tiles = [&](int it, int stage) {
        int kc = it * 16;
#pragma unroll
        for (int rep = 0; rep < 2; ++rep) {
            int f = tid + rep * 256;
            int kk = f >> 5;
            int c4 = f & 31;
            // A
            unsigned dA = smem_u32(&As[stage][kk][c4 * 4]);
            cpasync16(dA, pwT + (size_t)(kc + kk) * DIMC + o0 + c4 * 4, 16);
            // B
            int c = kc + kk;
            unsigned dB = smem_u32(&Bs[stage][kk][c4 * 4]);
            const float* srcp;
            int bytes;
            if (c < DIMC) {
                srcp = s16 + (size_t)(b * DIMC + c) * NPIX + p0 + c4 * 4;
                bytes = 16;
            } else if (c < CIN) {
                srcp = guid + (size_t)(b * GC + (c - DIMC)) * NPIX + p0 + c4 * 4;
                bytes = 16;
            } else {
                srcp = s16;  // not dereferenced
                bytes = 0;
            }
            cpasync16(dB, srcp, bytes);
        }
        cp_commit();
    };

    load_tiles(0, 0);
    for (int it = 0; it < NKT; ++it) {
        int cur = it & 1;
        if (it + 1 < NKT) {
            load_tiles(it + 1, cur ^ 1);
            cp_wait<1>();
        } else {
            cp_wait<0>();
        }
        __syncthreads();
#pragma unroll
        for (int kk = 0; kk < 16; ++kk) {
            ulonglong2 a01 = *(const ulonglong2*)&As[cur][kk][ty * 8];
            ulonglong2 a23 = *(const ulonglong2*)&As[cur][kk][ty * 8 + 4];
            float4 bA = *(const float4*)&Bs[cur][kk][tx * 8];
            float4 bB = *(const float4*)&Bs[cur][kk][tx * 8 + 4];
            unsigned long long av[4] = {a01.x, a01.y, a23.x, a23.y};
            unsigned long long bv[8] = {dup2(bA.x), dup2(bA.y), dup2(bA.z), dup2(bA.w),
                                        dup2(bB.x), dup2(bB.y), dup2(bB.z), dup2(bB.w)};
#pragma unroll
            for (int m = 0; m < 4; ++m)
#pragma unroll
                for (int n = 0; n < 8; ++n)
                    acc[m][n] = ffma2(av[m], bv[n], acc[m][n]);
        }
        __syncthreads();
    }
    // epilogue: each acc pair = output rows (2mp, 2mp+1) within the 8-row strip
#pragma unroll
    for (int mp = 0; mp < 4; ++mp) {
        int r0 = o0 + ty * 8 + mp * 2;
        float bias0 = __ldg(&pb[r0]);
        float bias1 = __ldg(&pb[r0 + 1]);
        float lo[8], hi[8];
#pragma unroll
        for (int n = 0; n < 8; ++n) {
            lo[n] = lo2(acc[mp][n]) + bias0;
            hi[n] = hi2(acc[mp][n]) + bias1;
        }
        float* o_r0 = out + (size_t)(b * DIMC + r0) * NPIX + p0 + tx * 8;
        float* o_r1 = o_r0 + NPIX;
        *(float4*)o_r0 = make_float4(lo[0], lo[1], lo[2], lo[3]);
        *(float4*)(o_r0 + 4) = make_float4(lo[4], lo[5], lo[6], lo[7]);
        *(float4*)o_r1 = make_float4(hi[0], hi[1], hi[2], hi[3]);
        *(float4*)(o_r1 + 4) = make_float4(hi[4], hi[5], hi[6], hi[7]);
    }
}

// ---------------- driver ----------------
extern "C" void kernel_launch(void* const* d_in, const int* in_sizes, int n_in,
                              void* d_out, int out_size) {
    (void)in_sizes; (void)n_in; (void)out_size;
    const float* source = (const float*)d_in[0];
    const float* guid = (const float*)d_in[1];
    const float* proj_w = (const float*)d_in[18];
    const float* proj_b = (const float*)d_in[19];

    float *s2, *s4, *s8, *s16, *gres, *comp, *maskb, *wtb, *pwT;
    cudaGetSymbolAddress((void**)&s2, d_s2);
    cudaGetSymbolAddress((void**)&s4, d_s4);
    cudaGetSymbolAddress((void**)&s8, d_s8);
    cudaGetSymbolAddress((void**)&s16, d_s16);
    cudaGetSymbolAddress((void**)&gres, d_gres);
    cudaGetSymbolAddress((void**)&comp, d_comp);
    cudaGetSymbolAddress((void**)&maskb, d_maskb);
    cudaGetSymbolAddress((void**)&wtb, d_wt);
    cudaGetSymbolAddress((void**)&pwT, d_pwT);

    cudaFuncSetAttribute(comp_kernel, cudaFuncAttributeMaxDynamicSharedMemorySize,
                         CIN * CC * 4);
    cudaFuncSetAttribute(mask_kernel, cudaFuncAttributeMaxDynamicSharedMemorySize,
                         CC * 9 * 36 * 4);

    const float* cur = source;
    float* outs[4] = {s2, s4, s8, s16};
    const int hs[4] = {14, 28, 56, 112};
    for (int s = 0; s < 4; ++s) {
        int h = hs[s], hw = h * h, H = 2 * h, HW = H * H;
        const float* cw = (const float*)d_in[2 + 4 * s];
        const float* cb = (const float*)d_in[3 + 4 * s];
        const float* ew = (const float*)d_in[4 + 4 * s];
        const float* eb = (const float*)d_in[5 + 4 * s];
        resize_kernel<<<(NB * GC * hw + 255) / 256, 256>>>(guid, gres, h);
        comp_kernel<<<dim3((hw + 127) / 128, NB), 128, CIN * CC * 4>>>(cur, gres, cw, cb,
                                                                       comp, hw);
        mask_kernel<<<dim3((hw + 127) / 128, NB), 128, CC * 9 * 36 * 4>>>(comp, ew, eb,
                                                                          maskb, h);
        softmax_shuffle_kernel<<<(NB * HW + 255) / 256, 256>>>(maskb, wtb, h);
        carafe_kernel<<<dim3((H + 31) / 32, (H + 15) / 16, NB), 256>>>(cur, wtb, outs[s], h);
        cur = outs[s];
    }
    transpose_w_kernel<<<(KPAD * DIMC + 255) / 256, 256>>>(proj_w, pwT);
    proj_kernel<<<dim3(392, 3, NB), 256>>>(s16, guid, pwT, proj_b, (float*)d_out);
}

// round 5
// speedup vs baseline: 2.2929x; 1.2512x over previous
#include <cuda_runtime.h>

#define NB 4
#define DIMC 384
#define CC 64
#define GC 3
#define CIN 387
#define KPAD 400

// ---------------- scratch (device globals; no allocation allowed) ----------------
__device__ float d_s2[NB * DIMC * 28 * 28];
__device__ float d_s4[NB * DIMC * 56 * 56];
__device__ float d_s8[NB * DIMC * 112 * 112];
__device__ float d_s16[NB * DIMC * 224 * 224];
__device__ float d_gres[NB * GC * 112 * 112];
__device__ float d_comp[NB * CC * 112 * 112];
__device__ float d_maskb[NB * 36 * 112 * 112];
__device__ float d_wt[NB * 9 * 224 * 224];
__device__ float d_pwT[KPAD * DIMC];

// ---------------- packed f32x2 helpers (Blackwell FFMA2) ----------------
__device__ __forceinline__ unsigned long long ffma2(unsigned long long a,
                                                    unsigned long long b,
                                                    unsigned long long c) {
    unsigned long long d;
    asm("fma.rn.f32x2 %0, %1, %2, %3;" : "=l"(d) : "l"(a), "l"(b), "l"(c));
    return d;
}
__device__ __forceinline__ unsigned long long pack2(float lo, float hi) {
    unsigned long long d;
    asm("mov.b64 %0, {%1, %2};" : "=l"(d) : "f"(lo), "f"(hi));
    return d;
}
__device__ __forceinline__ unsigned long long dup2(float v) {
    unsigned long long d;
    asm("mov.b64 %0, {%1, %1};" : "=l"(d) : "f"(v));
    return d;
}
__device__ __forceinline__ float lo2(unsigned long long v) {
    return __uint_as_float((unsigned)(v & 0xffffffffull));
}
__device__ __forceinline__ float hi2(unsigned long long v) {
    return __uint_as_float((unsigned)(v >> 32));
}

// ---------------- cp.async helpers ----------------
__device__ __forceinline__ unsigned smem_u32(const void* p) {
    unsigned a;
    asm("{ .reg .u64 t; cvta.to.shared.u64 t, %1; cvt.u32.u64 %0, t; }"
        : "=r"(a) : "l"(p));
    return a;
}
__device__ __forceinline__ void cpasync16(unsigned dst, const void* src, int srcbytes) {
    asm volatile("cp.async.ca.shared.global [%0], [%1], 16, %2;"
                 :: "r"(dst), "l"(src), "r"(srcbytes));
}
__device__ __forceinline__ void cp_commit() {
    asm volatile("cp.async.commit_group;");
}
template <int N>
__device__ __forceinline__ void cp_wait() {
    asm volatile("cp.async.wait_group %0;" :: "n"(N));
}

// ---------------- bilinear resize matching jax.image.resize (antialias=True) ----------------
__global__ void resize_kernel(const float* __restrict__ g, float* __restrict__ out, int h) {
    int idx = blockIdx.x * blockDim.x + threadIdx.x;
    int total = NB * GC * h * h;
    if (idx >= total) return;
    int j = idx % h;
    int t = idx / h;
    int i = t % h;
    int bc = t / h;
    float scale = (float)h / 224.0f;   // out/in (<1 downsample)
    float inv = 224.0f / (float)h;     // kernel support radius
    float si = (i + 0.5f) * inv - 0.5f;
    float sj = (j + 0.5f) * inv - 0.5f;
    int i0 = max(0, (int)floorf(si - inv) + 1);
    int i1 = min(223, (int)ceilf(si + inv) - 1);
    int j0 = max(0, (int)floorf(sj - inv) + 1);
    int j1 = min(223, (int)ceilf(sj + inv) - 1);
    const float* gp = g + (size_t)bc * 224 * 224;
    float wj_sum = 0.f;
    for (int jj = j0; jj <= j1; ++jj)
        wj_sum += fmaxf(0.f, 1.f - fabsf((float)jj - sj) * scale);
    float wi_sum = 0.f, acc = 0.f;
    for (int ii = i0; ii <= i1; ++ii) {
        float wi = fmaxf(0.f, 1.f - fabsf((float)ii - si) * scale);
        wi_sum += wi;
        if (wi > 0.f) {
            float row = 0.f;
            const float* rp = gp + ii * 224;
            for (int jj = j0; jj <= j1; ++jj) {
                float wj = fmaxf(0.f, 1.f - fabsf((float)jj - sj) * scale);
                row += wj * rp[jj];
            }
            acc += wi * row;
        }
    }
    out[idx] = acc / (wi_sum * wj_sum);
}

// ---------------- comp: 1x1 conv 387 -> 64 ----------------
// 256 threads: 128 pixels x 2 output-halves (32 outputs each).
// Channel loop unrolled x8 for MLP=8 on the strided input loads.
__global__ __launch_bounds__(256) void comp_kernel(const float* __restrict__ src,
                                                   const float* __restrict__ gres,
                                                   const float* __restrict__ cw,
                                                   const float* __restrict__ cb,
                                                   float* __restrict__ comp, int hw) {
    extern __shared__ float sW[]; // [CIN][CC]
    int tid = threadIdx.x;
    for (int i = tid; i < CIN * CC; i += 256) {
        int c = i >> 6, o = i & 63;
        sW[i] = cw[o * CIN + c];
    }
    __syncthreads();
    int half = tid >> 7;           // 0 or 1: which 32 output channels
    int pix = blockIdx.x * 128 + (tid & 127);
    int b = blockIdx.y;
    if (pix >= hw) return;

    unsigned long long acc[16];
#pragma unroll
    for (int p = 0; p < 16; ++p)
        acc[p] = pack2(__ldg(&cb[half * 32 + 2 * p]), __ldg(&cb[half * 32 + 2 * p + 1]));

    const float* sp = src + (size_t)b * DIMC * hw + pix;
#pragma unroll 1
    for (int c0 = 0; c0 < DIMC; c0 += 8) {
        float v[8];
#pragma unroll
        for (int u = 0; u < 8; ++u) v[u] = sp[(size_t)(c0 + u) * hw];
#pragma unroll
        for (int u = 0; u < 8; ++u) {
            unsigned long long vv = dup2(v[u]);
            const ulonglong2* w2 = (const ulonglong2*)&sW[(c0 + u) * CC + half * 32];
#pragma unroll
            for (int q = 0; q < 8; ++q) {
                ulonglong2 w = w2[q];
                acc[2 * q] = ffma2(vv, w.x, acc[2 * q]);
                acc[2 * q + 1] = ffma2(vv, w.y, acc[2 * q + 1]);
            }
        }
    }
    const float* gp = gres + (size_t)b * GC * hw + pix;
#pragma unroll
    for (int c = 0; c < GC; ++c) {
        unsigned long long vv = dup2(gp[(size_t)c * hw]);
        const ulonglong2* w2 = (const ulonglong2*)&sW[(DIMC + c) * CC + half * 32];
#pragma unroll
        for (int q = 0; q < 8; ++q) {
            ulonglong2 w = w2[q];
            acc[2 * q] = ffma2(vv, w.x, acc[2 * q]);
            acc[2 * q + 1] = ffma2(vv, w.y, acc[2 * q + 1]);
        }
    }
    float* op = comp + ((size_t)b * CC + half * 32) * hw + pix;
#pragma unroll
    for (int p = 0; p < 16; ++p) {
        op[(size_t)(2 * p) * hw] = lo2(acc[p]);
        op[(size_t)(2 * p + 1) * hw] = hi2(acc[p]);
    }
}

// ---------------- mask: 3x3 conv 64 -> 36, pad 1 ----------------
// 256 threads, channel pairs unrolled (18 global loads in flight).
__global__ __launch_bounds__(256) void mask_kernel(const float* __restrict__ comp,
                                                   const float* __restrict__ ew,
                                                   const float* __restrict__ eb,
                                                   float* __restrict__ maskb, int h) {
    extern __shared__ float sE[]; // [CC][9][36]
    int tid = threadIdx.x;
    for (int i = tid; i < CC * 9 * 36; i += 256) {
        int m = i % 36;
        int ck = i / 36;
        int k = ck % 9;
        int c = ck / 9;
        sE[i] = ew[(m * CC + c) * 9 + k];
    }
    __syncthreads();
    int hw = h * h;
    int pix = blockIdx.x * 256 + tid;
    int b = blockIdx.y;
    if (pix >= hw) return;
    int i = pix / h, j = pix % h;

    unsigned long long acc[18];
#pragma unroll
    for (int p = 0; p < 18; ++p)
        acc[p] = pack2(__ldg(&eb[2 * p]), __ldg(&eb[2 * p + 1]));

    int offs[9];
    bool val[9];
#pragma unroll
    for (int k = 0; k < 9; ++k) {
        int di = k / 3 - 1, dj = k % 3 - 1;
        int ii = i + di, jj = j + dj;
        val[k] = (ii >= 0) && (ii < h) && (jj >= 0) && (jj < h);
        offs[k] = val[k] ? (ii * h + jj) : 0;
    }
    const float* cp = comp + (size_t)b * CC * hw;
#pragma unroll 1
    for (int c0 = 0; c0 < CC; c0 += 2) {
        const float* cpa = cp + (size_t)c0 * hw;
        const float* cpb = cpa + hw;
        float va[9], vb[9];
#pragma unroll
        for (int k = 0; k < 9; ++k) {
            va[k] = val[k] ? cpa[offs[k]] : 0.f;
            vb[k] = val[k] ? cpb[offs[k]] : 0.f;
        }
#pragma unroll
        for (int k = 0; k < 9; ++k) {
            unsigned long long vv = dup2(va[k]);
            const ulonglong2* w2 = (const ulonglong2*)&sE[(c0 * 9 + k) * 36];
#pragma unroll
            for (int q = 0; q < 9; ++q) {
                ulonglong2 w = w2[q];
                acc[2 * q] = ffma2(vv, w.x, acc[2 * q]);
                acc[2 * q + 1] = ffma2(vv, w.y, acc[2 * q + 1]);
            }
        }
#pragma unroll
        for (int k = 0; k < 9; ++k) {
            unsigned long long vv = dup2(vb[k]);
            const ulonglong2* w2 = (const ulonglong2*)&sE[((c0 + 1) * 9 + k) * 36];
#pragma unroll
            for (int q = 0; q < 9; ++q) {
                ulonglong2 w = w2[q];
                acc[2 * q] = ffma2(vv, w.x, acc[2 * q]);
                acc[2 * q + 1] = ffma2(vv, w.y, acc[2 * q + 1]);
            }
        }
    }
    float* mp = maskb + (size_t)b * 36 * hw + pix;
#pragma unroll
    for (int p = 0; p < 18; ++p) {
        mp[(size_t)(2 * p) * hw] = lo2(acc[p]);
        mp[(size_t)(2 * p + 1) * hw] = hi2(acc[p]);
    }
}

// ---------------- pixel-shuffle + softmax over the 9 reassembly weights ----------------
__global__ void softmax_shuffle_kernel(const float* __restrict__ maskb,
                                       float* __restrict__ wt, int h) {
    int H = 2 * h;
    int HW = H * H, hw = h * h;
    int idx = blockIdx.x * blockDim.x + threadIdx.x;
    if (idx >= NB * HW) return;
    int J = idx % H;
    int t = idx / H;
    int I = t % H;
    int b = t / H;
    int i = I >> 1, p = I & 1, j = J >> 1, q = J & 1;
    const float* mp = maskb + ((size_t)b * 36 + (p * 2 + q)) * hw + i * h + j;
    float m[9], mx = -1e30f;
#pragma unroll
    for (int k = 0; k < 9; ++k) {
        m[k] = mp[(size_t)(k * 4) * hw];
        mx = fmaxf(mx, m[k]);
    }
    float s = 0.f;
#pragma unroll
    for (int k = 0; k < 9; ++k) {
        m[k] = __expf(m[k] - mx);
        s += m[k];
    }
    float inv = 1.f / s;
    float* wp = wt + (size_t)b * 9 * HW + I * H + J;
#pragma unroll
    for (int k = 0; k < 9; ++k) wp[(size_t)k * HW] = m[k] * inv;
}

// ---------------- CARAFE reassembly: register double-buffered channel chunks ----------------
#define CARAFE_CH 8
#define CARAFE_NE (CARAFE_CH * 180)  // 1440 smem elements per chunk
__global__ __launch_bounds__(256) void carafe_kernel(const float* __restrict__ src,
                                                     const float* __restrict__ wt,
                                                     float* __restrict__ out, int h) {
    int H = 2 * h, hw = h * h, HW = H * H;
    int b = blockIdx.z;
    int I0 = blockIdx.y * 16;
    int J0 = blockIdx.x * 32;
    int tid = threadIdx.x;
    int tx = tid & 15, ty = tid >> 4;
    __shared__ float xs[CARAFE_CH][10][18];

    int I = I0 + ty;
    int J1 = J0 + tx, J2 = J0 + tx + 16;
    bool v1 = (I < H) && (J1 < H);
    bool v2 = (I < H) && (J2 < H);
    float w1[9], w2[9];
    const float* wb = wt + (size_t)b * 9 * HW;
#pragma unroll
    for (int k = 0; k < 9; ++k) {
        w1[k] = v1 ? wb[(size_t)k * HW + I * H + J1] : 0.f;
        w2[k] = v2 ? wb[(size_t)k * HW + I * H + J2] : 0.f;
    }
    int i0 = I0 >> 1, j0 = J0 >> 1;
    int li = (ty >> 1) + 1;
    int lj1 = (tx >> 1) + 1;
    int lj2 = ((tx + 16) >> 1) + 1;
    const float* sb = src + (size_t)b * DIMC * hw;
    float* ob = out + (size_t)b * DIMC * HW;

    // per-thread load assignment (<= 6 elements of each chunk)
    int loff[6];
    int sflat[6];
    bool vld[6];
    int cnt = 0;
    for (int e = tid; e < CARAFE_NE; e += 256) {
        int c = e / 180;
        int r = e % 180;
        int ii = r / 18, jj = r % 18;
        int gi = i0 - 1 + ii, gj = j0 - 1 + jj;
        bool v = (gi >= 0) && (gi < h) && (gj >= 0) && (gj < h);
        loff[cnt] = c * hw + (v ? (gi * h + gj) : 0);
        sflat[cnt] = e;
        vld[cnt] = v;
        cnt++;
    }
    float rv[6];
#pragma unroll
    for (int q = 0; q < 6; ++q)
        rv[q] = (q < cnt && vld[q]) ? __ldg(sb + loff[q]) : 0.f;

    float* xsf = &xs[0][0][0];
    for (int cc = 0; cc < DIMC; cc += CARAFE_CH) {
        __syncthreads();  // previous chunk's compute done reading xs
#pragma unroll
        for (int q = 0; q < 6; ++q)
            if (q < cnt) xsf[sflat[q]] = rv[q];
        __syncthreads();
        if (cc + CARAFE_CH < DIMC) {
            const float* sbc = sb + (size_t)(cc + CARAFE_CH) * hw;
#pragma unroll
            for (int q = 0; q < 6; ++q)
                rv[q] = (q < cnt && vld[q]) ? __ldg(sbc + loff[q]) : 0.f;
        }
#pragma unroll
        for (int c = 0; c < CARAFE_CH; ++c) {
            float a1 = 0.f, a2 = 0.f;
#pragma unroll
            for (int k = 0; k < 9; ++k) {
                int di = k / 3, dj = k % 3;
                a1 += w1[k] * xs[c][li - 1 + di][lj1 - 1 + dj];
                a2 += w2[k] * xs[c][li - 1 + di][lj2 - 1 + dj];
            }
            if (v1) ob[(size_t)(cc + c) * HW + I * H + J1] = a1;
            if (v2) ob[(size_t)(cc + c) * HW + I * H + J2] = a2;
        }
    }
}

// ---------------- transpose + zero-pad proj weights: pwT[c][o], c in [0,400) ----------------
__global__ void transpose_w_kernel(const float* __restrict__ pw, float* __restrict__ pwT) {
    int idx = blockIdx.x * blockDim.x + threadIdx.x;
    if (idx >= KPAD * DIMC) return;
    int o = idx % DIMC, c = idx / DIMC;
    pwT[idx] = (c < CIN) ? pw[o * CIN + c] : 0.f;
}

// ---------------- final 1x1 conv = GEMM [384x387]x[387x50176] per batch, FFMA2 ----------------
#define NKT (KPAD / 16)
__global__ __launch_bounds__(256, 2) void proj_kernel(const float* __restrict__ s16,
                                                      const float* __restrict__ guid,
                                                      const float* __restrict__ pwT,
                                                      const float* __restrict__ pb,
                                                      float* __restrict__ out) {
    __shared__ float As[2][16][128];
    __shared__ float Bs[2][16][128];
    const int tid = threadIdx.x;
    const int tx = tid & 15, ty = tid >> 4;
    const int b = blockIdx.z;
    const int o0 = blockIdx.y * 128;
    const int p0 = blockIdx.x * 128;
    const size_t NPIX = 50176;

    unsigned long long acc[4][8];
#pragma unroll
    for (int m = 0; m < 4; ++m)
#pragma unroll
        for (int n = 0; n < 8; ++n) acc[m][n] = 0ull;

    auto load_tiles = [&](int it, int stage) {
        int kc = it * 16;
#pragma unroll
        for (int rep = 0; rep < 2; ++rep) {
            int f = tid + rep * 256;
            int kk = f >> 5;
            int c4 = f & 31;
            unsigned dA = smem_u32(&As[stage][kk][c4 * 4]);
            cpasync16(dA, pwT + (size_t)(kc + kk) * DIMC + o0 + c4 * 4, 16);
            int c = kc + kk;
            unsigned dB = smem_u32(&Bs[stage][kk][c4 * 4]);
            const float* srcp;
            int bytes;
            if (c < DIMC) {
                srcp = s16 + (size_t)(b * DIMC + c) * NPIX + p0 + c4 * 4;
                bytes = 16;
            } else if (c < CIN) {
                srcp = guid + (size_t)(b * GC + (c - DIMC)) * NPIX + p0 + c4 * 4;
                bytes = 16;
            } else {
                srcp = s16;  // not dereferenced
                bytes = 0;
            }
            cpasync16(dB, srcp, bytes);
        }
        cp_commit();
    };

    load_tiles(0, 0);
    for (int it = 0; it < NKT; ++it) {
        int cur = it & 1;
        if (it + 1 < NKT) {
            load_tiles(it + 1, cur ^ 1);
            cp_wait<1>();
        } else {
            cp_wait<0>();
        }
        __syncthreads();
#pragma unroll
        for (int kk = 0; kk < 16; ++kk) {
            ulonglong2 a01 = *(const ulonglong2*)&As[cur][kk][ty * 8];
            ulonglong2 a23 = *(const ulonglong2*)&As[cur][kk][ty * 8 + 4];
            float4 bA = *(const float4*)&Bs[cur][kk][tx * 8];
            float4 bB = *(const float4*)&Bs[cur][kk][tx * 8 + 4];
            unsigned long long av[4] = {a01.x, a01.y, a23.x, a23.y};
            unsigned long long bv[8] = {dup2(bA.x), dup2(bA.y), dup2(bA.z), dup2(bA.w),
                                        dup2(bB.x), dup2(bB.y), dup2(bB.z), dup2(bB.w)};
#pragma unroll
            for (int m = 0; m < 4; ++m)
#pragma unroll
                for (int n = 0; n < 8; ++n)
                    acc[m][n] = ffma2(av[m], bv[n], acc[m][n]);
        }
        __syncthreads();
    }
#pragma unroll
    for (int mp = 0; mp < 4; ++mp) {
        int r0 = o0 + ty * 8 + mp * 2;
        float bias0 = __ldg(&pb[r0]);
        float bias1 = __ldg(&pb[r0 + 1]);
        float lo[8], hi[8];
#pragma unroll
        for (int n = 0; n < 8; ++n) {
            lo[n] = lo2(acc[mp][n]) + bias0;
            hi[n] = hi2(acc[mp][n]) + bias1;
        }
        float* o_r0 = out + (size_t)(b * DIMC + r0) * NPIX + p0 + tx * 8;
        float* o_r1 = o_r0 + NPIX;
        *(float4*)o_r0 = make_float4(lo[0], lo[1], lo[2], lo[3]);
        *(float4*)(o_r0 + 4) = make_float4(lo[4], lo[5], lo[6], lo[7]);
        *(float4*)o_r1 = make_float4(hi[0], hi[1], hi[2], hi[3]);
        *(float4*)(o_r1 + 4) = make_float4(hi[4], hi[5], hi[6], hi[7]);
    }
}

// ---------------- driver ----------------
extern "C" void kernel_launch(void* const* d_in, const int* in_sizes, int n_in,
                              void* d_out, int out_size) {
    (void)in_sizes; (void)n_in; (void)out_size;
    const float* source = (const float*)d_in[0];
    const float* guid = (const float*)d_in[1];
    const float* proj_w = (const float*)d_in[18];
    const float* proj_b = (const float*)d_in[19];

    float *s2, *s4, *s8, *s16, *gres, *comp, *maskb, *wtb, *pwT;
    cudaGetSymbolAddress((void**)&s2, d_s2);
    cudaGetSymbolAddress((void**)&s4, d_s4);
    cudaGetSymbolAddress((void**)&s8, d_s8);
    cudaGetSymbolAddress((void**)&s16, d_s16);
    cudaGetSymbolAddress((void**)&gres, d_gres);
    cudaGetSymbolAddress((void**)&comp, d_comp);
    cudaGetSymbolAddress((void**)&maskb, d_maskb);
    cudaGetSymbolAddress((void**)&wtb, d_wt);
    cudaGetSymbolAddress((void**)&pwT, d_pwT);

    cudaFuncSetAttribute(comp_kernel, cudaFuncAttributeMaxDynamicSharedMemorySize,
                         CIN * CC * 4);
    cudaFuncSetAttribute(mask_kernel, cudaFuncAttributeMaxDynamicSharedMemorySize,
                         CC * 9 * 36 * 4);

    const float* cur = source;
    float* outs[4] = {s2, s4, s8, s16};
    const int hs[4] = {14, 28, 56, 112};
    for (int s = 0; s < 4; ++s) {
        int h = hs[s], hw = h * h, H = 2 * h, HW = H * H;
        const float* cw = (const float*)d_in[2 + 4 * s];
        const float* cb = (const float*)d_in[3 + 4 * s];
        const float* ew = (const float*)d_in[4 + 4 * s];
        const float* eb = (const float*)d_in[5 + 4 * s];
        resize_kernel<<<(NB * GC * hw + 255) / 256, 256>>>(guid, gres, h);
        comp_kernel<<<dim3((hw + 127) / 128, NB), 256, CIN * CC * 4>>>(cur, gres, cw, cb,
                                                                       comp, hw);
        mask_kernel<<<dim3((hw + 255) / 256, NB), 256, CC * 9 * 36 * 4>>>(comp, ew, eb,
                                                                          maskb, h);
        softmax_shuffle_kernel<<<(NB * HW + 255) / 256, 256>>>(maskb, wtb, h);
        carafe_kernel<<<dim3((H + 31) / 32, (H + 15) / 16, NB), 256>>>(cur, wtb, outs[s], h);
        cur = outs[s];
    }
    transpose_w_kernel<<<(KPAD * DIMC + 255) / 256, 256>>>(proj_w, pwT);
    proj_kernel<<<dim3(392, 3, NB), 256>>>(s16, guid, pwT, proj_b, (float*)d_out);
}

// round 9
// speedup vs baseline: 3.0945x; 1.3496x over previous
#include <cuda_runtime.h>
#include <cuda_bf16.h>
#include <cstdint>

#define NB 4
#define DIMC 384
#define CC 64
#define GC 3
#define CIN 387
#define NKC 13           /* 13 k-chunks of 32 -> K=416 */

// ---------------- scratch (device globals; no allocation allowed) ----------------
__device__ float d_s2[NB * DIMC * 28 * 28];
__device__ float d_s4[NB * DIMC * 56 * 56];
__device__ float d_s8[NB * DIMC * 112 * 112];
__device__ float d_s16[NB * DIMC * 224 * 224];
__device__ float d_gres[NB * GC * 112 * 112];
__device__ float d_comp[NB * CC * 112 * 112];
__device__ float d_maskb[NB * 36 * 112 * 112];
__device__ float d_wt[NB * 9 * 224 * 224];
// pre-packed bf16-split proj weights: 3 o-tiles x 13 k-chunks x [128m x 32k]
__device__ __align__(16) __nv_bfloat16 d_pwA1[3 * NKC * 4096];
__device__ __align__(16) __nv_bfloat16 d_pwA2[3 * NKC * 4096];

// ---------------- packed f32x2 helpers (Blackwell FFMA2) ----------------
__device__ __forceinline__ unsigned long long ffma2(unsigned long long a,
                                                    unsigned long long b,
                                                    unsigned long long c) {
    unsigned long long d;
    asm("fma.rn.f32x2 %0, %1, %2, %3;" : "=l"(d) : "l"(a), "l"(b), "l"(c));
    return d;
}
__device__ __forceinline__ unsigned long long pack2(float lo, float hi) {
    unsigned long long d;
    asm("mov.b64 %0, {%1, %2};" : "=l"(d) : "f"(lo), "f"(hi));
    return d;
}
__device__ __forceinline__ unsigned long long dup2(float v) {
    unsigned long long d;
    asm("mov.b64 %0, {%1, %1};" : "=l"(d) : "f"(v));
    return d;
}
__device__ __forceinline__ float lo2(unsigned long long v) {
    return __uint_as_float((unsigned)(v & 0xffffffffull));
}
__device__ __forceinline__ float hi2(unsigned long long v) {
    return __uint_as_float((unsigned)(v >> 32));
}

// ---------------- smem / async helpers ----------------
__device__ __forceinline__ unsigned smem_u32(const void* p) {
    unsigned a;
    asm("{ .reg .u64 t; cvta.to.shared.u64 t, %1; cvt.u32.u64 %0, t; }"
        : "=r"(a) : "l"(p));
    return a;
}
__device__ __forceinline__ void cpasync16(unsigned dst, const void* src) {
    asm volatile("cp.async.ca.shared.global [%0], [%1], 16;"
                 :: "r"(dst), "l"(src));
}
__device__ __forceinline__ void cp_commit() {
    asm volatile("cp.async.commit_group;");
}
template <int N>
__device__ __forceinline__ void cp_wait() {
    asm volatile("cp.async.wait_group %0;" :: "n"(N));
}

// ---------------- mma.sync helpers ----------------
__device__ __forceinline__ void ldsm_x4(uint32_t* r, uint32_t addr) {
    asm volatile("ldmatrix.sync.aligned.m8n8.x4.shared.b16 {%0,%1,%2,%3}, [%4];"
                 : "=r"(r[0]), "=r"(r[1]), "=r"(r[2]), "=r"(r[3]) : "r"(addr));
}
__device__ __forceinline__ void mma_bf16(float* d, const uint32_t* a, const uint32_t* b) {
    asm volatile(
        "mma.sync.aligned.m16n8k16.row.col.f32.bf16.bf16.f32 "
        "{%0,%1,%2,%3}, {%4,%5,%6,%7}, {%8,%9}, {%0,%1,%2,%3};"
        : "+f"(d[0]), "+f"(d[1]), "+f"(d[2]), "+f"(d[3])
        : "r"(a[0]), "r"(a[1]), "r"(a[2]), "r"(a[3]), "r"(b[0]), "r"(b[1]));
}

// ---------------- bilinear resize matching jax.image.resize (antialias=True) ----------------
__global__ void resize_kernel(const float* __restrict__ g, float* __restrict__ out, int h) {
    int idx = blockIdx.x * blockDim.x + threadIdx.x;
    int total = NB * GC * h * h;
    if (idx >= total) return;
    int j = idx % h;
    int t = idx / h;
    int i = t % h;
    int bc = t / h;
    float scale = (float)h / 224.0f;
    float inv = 224.0f / (float)h;
    float si = (i + 0.5f) * inv - 0.5f;
    float sj = (j + 0.5f) * inv - 0.5f;
    int i0 = max(0, (int)floorf(si - inv) + 1);
    int i1 = min(223, (int)ceilf(si + inv) - 1);
    int j0 = max(0, (int)floorf(sj - inv) + 1);
    int j1 = min(223, (int)ceilf(sj + inv) - 1);
    const float* gp = g + (size_t)bc * 224 * 224;
    float wj_sum = 0.f;
    for (int jj = j0; jj <= j1; ++jj)
        wj_sum += fmaxf(0.f, 1.f - fabsf((float)jj - sj) * scale);
    float wi_sum = 0.f, acc = 0.f;
    for (int ii = i0; ii <= i1; ++ii) {
        float wi = fmaxf(0.f, 1.f - fabsf((float)ii - si) * scale);
        wi_sum += wi;
        if (wi > 0.f) {
            float row = 0.f;
            const float* rp = gp + ii * 224;
            for (int jj = j0; jj <= j1; ++jj) {
                float wj = fmaxf(0.f, 1.f - fabsf((float)jj - sj) * scale);
                row += wj * rp[jj];
            }
            acc += wi * row;
        }
    }
    out[idx] = acc / (wi_sum * wj_sum);
}

// ---------------- comp: 1x1 conv 387 -> 64 ----------------
__global__ __launch_bounds__(256) void comp_kernel(const float* __restrict__ src,
                                                   const float* __restrict__ gres,
                                                   const float* __restrict__ cw,
                                                   const float* __restrict__ cb,
                                                   float* __restrict__ comp, int hw) {
    extern __shared__ float sW[]; // [CIN][CC]
    int tid = threadIdx.x;
    for (int i = tid; i < CIN * CC; i += 256) {
        int c = i >> 6, o = i & 63;
        sW[i] = cw[o * CIN + c];
    }
    __syncthreads();
    int half = tid >> 7;
    int pix = blockIdx.x * 128 + (tid & 127);
    int b = blockIdx.y;
    if (pix >= hw) return;

    unsigned long long acc[16];
#pragma unroll
    for (int p = 0; p < 16; ++p)
        acc[p] = pack2(__ldg(&cb[half * 32 + 2 * p]), __ldg(&cb[half * 32 + 2 * p + 1]));

    const float* sp = src + (size_t)b * DIMC * hw + pix;
#pragma unroll 1
    for (int c0 = 0; c0 < DIMC; c0 += 8) {
        float v[8];
#pragma unroll
        for (int u = 0; u < 8; ++u) v[u] = sp[(size_t)(c0 + u) * hw];
#pragma unroll
        for (int u = 0; u < 8; ++u) {
            unsigned long long vv = dup2(v[u]);
            const ulonglong2* w2 = (const ulonglong2*)&sW[(c0 + u) * CC + half * 32];
#pragma unroll
            for (int q = 0; q < 8; ++q) {
                ulonglong2 w = w2[q];
                acc[2 * q] = ffma2(vv, w.x, acc[2 * q]);
                acc[2 * q + 1] = ffma2(vv, w.y, acc[2 * q + 1]);
            }
        }
    }
    const float* gp = gres + (size_t)b * GC * hw + pix;
#pragma unroll
    for (int c = 0; c < GC; ++c) {
        unsigned long long vv = dup2(gp[(size_t)c * hw]);
        const ulonglong2* w2 = (const ulonglong2*)&sW[(DIMC + c) * CC + half * 32];
#pragma unroll
        for (int q = 0; q < 8; ++q) {
            ulonglong2 w = w2[q];
            acc[2 * q] = ffma2(vv, w.x, acc[2 * q]);
            acc[2 * q + 1] = ffma2(vv, w.y, acc[2 * q + 1]);
        }
    }
    float* op = comp + ((size_t)b * CC + half * 32) * hw + pix;
#pragma unroll
    for (int p = 0; p < 16; ++p) {
        op[(size_t)(2 * p) * hw] = lo2(acc[p]);
        op[(size_t)(2 * p + 1) * hw] = hi2(acc[p]);
    }
}

// ---------------- mask: 3x3 conv 64 -> 36, pad 1 ----------------
__global__ __launch_bounds__(256) void mask_kernel(const float* __restrict__ comp,
                                                   const float* __restrict__ ew,
                                                   const float* __restrict__ eb,
                                                   float* __restrict__ maskb, int h) {
    extern __shared__ float sE[]; // [CC][9][36]
    int tid = threadIdx.x;
    for (int i = tid; i < CC * 9 * 36; i += 256) {
        int m = i % 36;
        int ck = i / 36;
        int k = ck % 9;
        int c = ck / 9;
        sE[i] = ew[(m * CC + c) * 9 + k];
    }
    __syncthreads();
    int hw = h * h;
    int pix = blockIdx.x * 256 + tid;
    int b = blockIdx.y;
    if (pix >= hw) return;
    int i = pix / h, j = pix % h;

    unsigned long long acc[18];
#pragma unroll
    for (int p = 0; p < 18; ++p)
        acc[p] = pack2(__ldg(&eb[2 * p]), __ldg(&eb[2 * p + 1]));

    int offs[9];
    bool val[9];
#pragma unroll
    for (int k = 0; k < 9; ++k) {
        int di = k / 3 - 1, dj = k % 3 - 1;
        int ii = i + di, jj = j + dj;
        val[k] = (ii >= 0) && (ii < h) && (jj >= 0) && (jj < h);
        offs[k] = val[k] ? (ii * h + jj) : 0;
    }
    const float* cp = comp + (size_t)b * CC * hw;
#pragma unroll 1
    for (int c0 = 0; c0 < CC; c0 += 2) {
        const float* cpa = cp + (size_t)c0 * hw;
        const float* cpb = cpa + hw;
        float va[9], vb[9];
#pragma unroll
        for (int k = 0; k < 9; ++k) {
            va[k] = val[k] ? cpa[offs[k]] : 0.f;
            vb[k] = val[k] ? cpb[offs[k]] : 0.f;
        }
#pragma unroll
        for (int k = 0; k < 9; ++k) {
            unsigned long long vv = dup2(va[k]);
            const ulonglong2* w2 = (const ulonglong2*)&sE[(c0 * 9 + k) * 36];
#pragma unroll
            for (int q = 0; q < 9; ++q) {
                ulonglong2 w = w2[q];
                acc[2 * q] = ffma2(vv, w.x, acc[2 * q]);
                acc[2 * q + 1] = ffma2(vv, w.y, acc[2 * q + 1]);
            }
        }
#pragma unroll
        for (int k = 0; k < 9; ++k) {
            unsigned long long vv = dup2(vb[k]);
            const ulonglong2* w2 = (const ulonglong2*)&sE[((c0 + 1) * 9 + k) * 36];
#pragma unroll
            for (int q = 0; q < 9; ++q) {
                ulonglong2 w = w2[q];
                acc[2 * q] = ffma2(vv, w.x, acc[2 * q]);
                acc[2 * q + 1] = ffma2(vv, w.y, acc[2 * q + 1]);
            }
        }
    }
    float* mp = maskb + (size_t)b * 36 * hw + pix;
#pragma unroll
    for (int p = 0; p < 18; ++p) {
        mp[(size_t)(2 * p) * hw] = lo2(acc[p]);
        mp[(size_t)(2 * p + 1) * hw] = hi2(acc[p]);
    }
}

// ---------------- pixel-shuffle + softmax: quad-contiguous weight layout ----------------
// wt[((b*9 + k)*hw + i*h + j)*4 + (p*2+q)]
__global__ void softmax_shuffle_kernel(const float* __restrict__ maskb,
                                       float* __restrict__ wt, int h) {
    int H = 2 * h;
    int HW = H * H, hw = h * h;
    int idx = blockIdx.x * blockDim.x + threadIdx.x;
    if (idx >= NB * HW) return;
    int J = idx % H;
    int t = idx / H;
    int I = t % H;
    int b = t / H;
    int i = I >> 1, p = I & 1, j = J >> 1, q = J & 1;
    const float* mp = maskb + ((size_t)b * 36 + (p * 2 + q)) * hw + i * h + j;
    float m[9], mx = -1e30f;
#pragma unroll
    for (int k = 0; k < 9; ++k) {
        m[k] = mp[(size_t)(k * 4) * hw];
        mx = fmaxf(mx, m[k]);
    }
    float s = 0.f;
#pragma unroll
    for (int k = 0; k < 9; ++k) {
        m[k] = __expf(m[k] - mx);
        s += m[k];
    }
    float inv = 1.f / s;
    float* wp = wt + (((size_t)b * 9) * hw + i * h + j) * 4 + (p * 2 + q);
#pragma unroll
    for (int k = 0; k < 9; ++k) wp[(size_t)k * hw * 4] = m[k] * inv;
}

// ---------------- CARAFE reassembly: one thread per low-res pixel = 2x2 hi-res quad ----------------
#define CARAFE_CH 8
#define CARAFE_NE (CARAFE_CH * 324)  // 18x18 window per channel
__global__ __launch_bounds__(256) void carafe_kernel(const float* __restrict__ src,
                                                     const float* __restrict__ wt,
                                                     float* __restrict__ out, int h) {
    int H = 2 * h, hw = h * h, HW = H * H;
    int b = blockIdx.z;
    int i0 = blockIdx.y * 16;
    int j0 = blockIdx.x * 16;
    int tid = threadIdx.x;
    int ti = tid >> 4, tj = tid & 15;
    int i = i0 + ti, j = j0 + tj;
    bool valid = (i < h) && (j < h);
    __shared__ float xs[CARAFE_CH][18][18];

    float4 w4[9];
    {
        const float4* wb = (const float4*)(wt + (((size_t)b * 9) * hw + i * h + j) * 4);
#pragma unroll
        for (int k = 0; k < 9; ++k)
            w4[k] = valid ? wb[(size_t)k * hw] : make_float4(0.f, 0.f, 0.f, 0.f);
    }

    int loff[11], sflat[11];
    bool vld[11];
    int cnt = 0;
    for (int e = tid; e < CARAFE_NE; e += 256) {
        int c = e / 324;
        int r = e % 324;
        int ii = r / 18, jj = r % 18;
        int gi = i0 - 1 + ii, gj = j0 - 1 + jj;
        bool v = (gi >= 0) && (gi < h) && (gj >= 0) && (gj < h);
        loff[cnt] = c * hw + (v ? (gi * h + gj) : 0);
        sflat[cnt] = e;
        vld[cnt] = v;
        cnt++;
    }
    const float* sb = src + (size_t)b * DIMC * hw;
    float* ob = out + (size_t)b * DIMC * HW;
    float rv[11];
#pragma unroll
    for (int q = 0; q < 11; ++q)
        rv[q] = (q < cnt && vld[q]) ? __ldg(sb + loff[q]) : 0.f;

    float* xsf = &xs[0][0][0];
    int I = 2 * i, J = 2 * j;
    for (int cc = 0; cc < DIMC; cc += CARAFE_CH) {
        __syncthreads();
#pragma unroll
        for (int q = 0; q < 11; ++q)
            if (q < cnt) xsf[sflat[q]] = rv[q];
        __syncthreads();
        if (cc + CARAFE_CH < DIMC) {
            const float* sbc = sb + (size_t)(cc + CARAFE_CH) * hw;
#pragma unroll
            for (int q = 0; q < 11; ++q)
                rv[q] = (q < cnt && vld[q]) ? __ldg(sbc + loff[q]) : 0.f;
        }
#pragma unroll
        for (int c = 0; c < CARAFE_CH; ++c) {
            float a00 = 0.f, a01 = 0.f, a10 = 0.f, a11 = 0.f;
#pragma unroll
            for (int k = 0; k < 9; ++k) {
                float x = xs[c][ti + k / 3][tj + k % 3];
                a00 += w4[k].x * x;
                a01 += w4[k].y * x;
                a10 += w4[k].z * x;
                a11 += w4[k].w * x;
            }
            if (valid) {
                float* o0 = ob + (size_t)(cc + c) * HW + (size_t)I * H + J;
                *(float2*)o0 = make_float2(a00, a01);
                *(float2*)(o0 + H) = make_float2(a10, a11);
            }
        }
    }
}

// ---------------- pack proj weights into bf16-split [m][k] MMA tiles ----------------
__global__ void packw_kernel(const float* __restrict__ pw) {
    int idx = blockIdx.x * blockDim.x + threadIdx.x;
    if (idx >= 3 * NKC * 4096) return;
    int k = idx & 31;
    int m = (idx >> 5) & 127;
    int kt = idx >> 12;            // o*NKC + kc
    int o = kt / NKC, kc = kt % NKC;
    int c = kc * 32 + k;
    float w = (c < CIN) ? pw[(size_t)(o * 128 + m) * CIN + c] : 0.f;
    __nv_bfloat16 a1 = __float2bfloat16(w);
    __nv_bfloat16 a2 = __float2bfloat16(w - __bfloat162float(a1));
    int off = kt * 4096 + m * 32 + k;
    d_pwA1[off] = a1;
    d_pwA2[off] = a2;
}

// ---------------- final 1x1 conv: mma.sync bf16-split (3-term) GEMM ----------------
// BM=128 (out ch), BN=128 (px), BK=32, K=416. Smem rows [m|n][k], 40 bf16 (80B) stride.
// Stage layout: A1(10240) A2(10240) B1(10240) B2(10240); 2 stages = 81920 B.
#define ROWB 80
#define STAGE_SZ 40960
#define PJ_SMEM (2 * STAGE_SZ)
__global__ __launch_bounds__(256, 2) void proj_mma_kernel(const float* __restrict__ s16,
                                                          const float* __restrict__ guid,
                                                          const float* __restrict__ pb,
                                                          float* __restrict__ out) {
    extern __shared__ char smem[];
    const uint32_t sb = smem_u32(smem);
    const int tid = threadIdx.x;
    const int wid = tid >> 5, lane = tid & 31;
    const int wm = wid >> 2, wn = wid & 3;          // warp grid 2 x 4
    const int pt = blockIdx.x, ot = blockIdx.y, b = blockIdx.z;
    const size_t NPIX = 50176;
    const size_t p0 = (size_t)pt * 128;
    const int o0 = ot * 128;

    float acc[4][4][4];
#pragma unroll
    for (int mf = 0; mf < 4; ++mf)
#pragma unroll
        for (int nf = 0; nf < 4; ++nf)
#pragma unroll
            for (int r = 0; r < 4; ++r) acc[mf][nf][r] = 0.f;

    // B fill mapping: channel pair cp (0..15), pixel group pg (0..15) of 8 px
    const int cp = tid & 15, pg = tid >> 4;
    const int c0l = 2 * cp, px0 = pg * 8;

    // ldmatrix lane-address components
    const int a_row_l = lane & 15;                       // m row within frag
    const int a_kadd = (lane >> 4) << 4;                 // +16B for k+8 half
    const int b_row_l = (lane & 7) | ((lane & 16) >> 1); // n row within 16
    const int b_kadd = (lane & 8) << 1;                  // +16B for k+8 half

    // channel -> global row pointer (pixel-contiguous), or null for zero-fill
    auto chanp = [&](int c) -> const float* {
        if (c < DIMC) return s16 + ((size_t)(b * DIMC + c)) * NPIX + p0;
        if (c < CIN) return guid + ((size_t)(b * GC + (c - DIMC))) * NPIX + p0;
        return (const float*)0;
    };

    // ---- fill helpers ----
    auto a_issue = [&](int kc, int s) {
        const __nv_bfloat16* g1 = d_pwA1 + (ot * NKC + kc) * 4096;
        const __nv_bfloat16* g2 = d_pwA2 + (ot * NKC + kc) * 4096;
        uint32_t d1 = sb + s * STAGE_SZ;
        uint32_t d2 = d1 + 10240;
#pragma unroll
        for (int r = 0; r < 2; ++r) {
            int seg = tid + r * 256;           // 512 segments of 16B
            int row = seg >> 2, sg = seg & 3;
            cpasync16(d1 + row * ROWB + sg * 16, g1 + row * 32 + sg * 8);
            cpasync16(d2 + row * ROWB + sg * 16, g2 + row * 32 + sg * 8);
        }
        cp_commit();
    };
    float4 bf[4];
    auto b_issue = [&](int kc) {
        const float* r0 = chanp(kc * 32 + c0l);
        const float* r1 = chanp(kc * 32 + c0l + 1);
        float4 z = make_float4(0.f, 0.f, 0.f, 0.f);
        bf[0] = r0 ? __ldg((const float4*)(r0 + px0)) : z;
        bf[1] = r0 ? __ldg((const float4*)(r0 + px0 + 4)) : z;
        bf[2] = r1 ? __ldg((const float4*)(r1 + px0)) : z;
        bf[3] = r1 ? __ldg((const float4*)(r1 + px0 + 4)) : z;
    };
    auto b_store = [&](int s) {
        uint32_t b1 = sb + s * STAGE_SZ + 20480;
        uint32_t b2 = b1 + 10240;
        const float* f0 = &bf[0].x;   // channel c0l, px0..px0+7
        const float* f1 = &bf[2].x;   // channel c0l+1
#pragma unroll
        for (int i = 0; i < 8; ++i) {
            float v0 = f0[i], v1 = f1[i];
            __nv_bfloat16 h0 = __float2bfloat16(v0);
            __nv_bfloat16 h1 = __float2bfloat16(v1);
            __nv_bfloat16 l0 = __float2bfloat16(v0 - __bfloat162float(h0));
            __nv_bfloat16 l1 = __float2bfloat16(v1 - __bfloat162float(h1));
            uint32_t hp = (uint32_t)__bfloat16_as_ushort(h0) |
                          ((uint32_t)__bfloat16_as_ushort(h1) << 16);
            uint32_t lp = (uint32_t)__bfloat16_as_ushort(l0) |
                          ((uint32_t)__bfloat16_as_ushort(l1) << 16);
            uint32_t off = (uint32_t)(px0 + i) * ROWB + cp * 4;
            asm volatile("st.shared.b32 [%0], %1;" :: "r"(b1 + off), "r"(hp) : "memory");
            asm volatile("st.shared.b32 [%0], %1;" :: "r"(b2 + off), "r"(lp) : "memory");
        }
    };

    // prefill chunk 0
    a_issue(0, 0);
    b_issue(0);
    b_store(0);
    cp_wait<0>();
    __syncthreads();

    for (int kc = 0; kc < NKC; ++kc) {
        int s = kc & 1;
        if (kc + 1 < NKC) {
            a_issue(kc + 1, s ^ 1);   // async
            b_issue(kc + 1);          // LDGs in flight during compute
        }
        // ---- compute chunk kc from stage s ----
        uint32_t A1b = sb + s * STAGE_SZ;
        uint32_t A2b = A1b + 10240;
        uint32_t B1b = A1b + 20480;
        uint32_t B2b = A1b + 30720;
#pragma unroll
        for (int ks = 0; ks < 2; ++ks) {
            uint32_t koff = ks * 32;
            uint32_t aoff = (uint32_t)(wm * 64 + a_row_l) * ROWB + koff + a_kadd;
            uint32_t boff0 = (uint32_t)(wn * 32 + b_row_l) * ROWB + koff + b_kadd;
            uint32_t boff1 = boff0 + 16 * ROWB;
            uint32_t av[16], bv1[8], bv2[8];
            ldsm_x4(bv1, B1b + boff0);
            ldsm_x4(bv1 + 4, B1b + boff1);
#pragma unroll
            for (int mf = 0; mf < 4; ++mf)
                ldsm_x4(av + mf * 4, A1b + aoff + mf * 16 * ROWB);
            // A1 * B1
#pragma unroll
            for (int mf = 0; mf < 4; ++mf)
#pragma unroll
                for (int nf = 0; nf < 4; ++nf)
                    mma_bf16(acc[mf][nf], av + mf * 4, bv1 + nf * 2);
            // A1 * B2
            ldsm_x4(bv2, B2b + boff0);
            ldsm_x4(bv2 + 4, B2b + boff1);
#pragma unroll
            for (int mf = 0; mf < 4; ++mf)
#pragma unroll
                for (int nf = 0; nf < 4; ++nf)
                    mma_bf16(acc[mf][nf], av + mf * 4, bv2 + nf * 2);
            // A2 * B1 (reuse av regs)
#pragma unroll
            for (int mf = 0; mf < 4; ++mf)
                ldsm_x4(av + mf * 4, A2b + aoff + mf * 16 * ROWB);
#pragma unroll
            for (int mf = 0; mf < 4; ++mf)
#pragma unroll
                for (int nf = 0; nf < 4; ++nf)
                    mma_bf16(acc[mf][nf], av + mf * 4, bv1 + nf * 2);
        }
        if (kc + 1 < NKC) {
            b_store(s ^ 1);
            cp_wait<0>();
        }
        __syncthreads();
    }

    // ---- epilogue ----
#pragma unroll
    for (int mf = 0; mf < 4; ++mf) {
        int row0 = o0 + wm * 64 + mf * 16 + (lane >> 2);
        int row1 = row0 + 8;
        float bias0 = __ldg(&pb[row0]);
        float bias1 = __ldg(&pb[row1]);
        float* ob0 = out + ((size_t)(b * DIMC + row0)) * NPIX + p0 + wn * 32 + (lane & 3) * 2;
        float* ob1 = out + ((size_t)(b * DIMC + row1)) * NPIX + p0 + wn * 32 + (lane & 3) * 2;
#pragma unroll
        for (int nf = 0; nf < 4; ++nf) {
            *(float2*)(ob0 + nf * 8) = make_float2(acc[mf][nf][0] + bias0,
                                                   acc[mf][nf][1] + bias0);
            *(float2*)(ob1 + nf * 8) = make_float2(acc[mf][nf][2] + bias1,
                                                   acc[mf][nf][3] + bias1);
        }
    }
}

// ---------------- driver ----------------
extern "C" void kernel_launch(void* const* d_in, const int* in_sizes, int n_in,
                              void* d_out, int out_size) {
    (void)in_sizes; (void)n_in; (void)out_size;
    const float* source = (const float*)d_in[0];
    const float* guid = (const float*)d_in[1];
    const float* proj_w = (const float*)d_in[18];
    const float* proj_b = (const float*)d_in[19];

    float *s2, *s4, *s8, *s16, *gres, *comp, *maskb, *wtb;
    cudaGetSymbolAddress((void**)&s2, d_s2);
    cudaGetSymbolAddress((void**)&s4, d_s4);
    cudaGetSymbolAddress((void**)&s8, d_s8);
    cudaGetSymbolAddress((void**)&s16, d_s16);
    cudaGetSymbolAddress((void**)&gres, d_gres);
    cudaGetSymbolAddress((void**)&comp, d_comp);
    cudaGetSymbolAddress((void**)&maskb, d_maskb);
    cudaGetSymbolAddress((void**)&wtb, d_wt);

    cudaFuncSetAttribute(comp_kernel, cudaFuncAttributeMaxDynamicSharedMemorySize,
                         CIN * CC * 4);
    cudaFuncSetAttribute(mask_kernel, cudaFuncAttributeMaxDynamicSharedMemorySize,
                         CC * 9 * 36 * 4);
    cudaFuncSetAttribute(proj_mma_kernel, cudaFuncAttributeMaxDynamicSharedMemorySize,
                         PJ_SMEM);

    const float* cur = source;
    float* outs[4] = {s2, s4, s8, s16};
    const int hs[4] = {14, 28, 56, 112};
    for (int s = 0; s < 4; ++s) {
        int h = hs[s], hw = h * h, H = 2 * h, HW = H * H;
        const float* cw = (const float*)d_in[2 + 4 * s];
        const float* cb = (const float*)d_in[3 + 4 * s];
        const float* ew = (const float*)d_in[4 + 4 * s];
        const float* eb = (const float*)d_in[5 + 4 * s];
        resize_kernel<<<(NB * GC * hw + 255) / 256, 256>>>(guid, gres, h);
        comp_kernel<<<dim3((hw + 127) / 128, NB), 256, CIN * CC * 4>>>(cur, gres, cw, cb,
                                                                       comp, hw);
        mask_kernel<<<dim3((hw + 255) / 256, NB), 256, CC * 9 * 36 * 4>>>(comp, ew, eb,
                                                                          maskb, h);
        softmax_shuffle_kernel<<<(NB * HW + 255) / 256, 256>>>(maskb, wtb, h);
        int nt = (h + 15) / 16;
        carafe_kernel<<<dim3(nt, nt, NB), 256>>>(cur, wtb, outs[s], h);
        cur = outs[s];
    }
    packw_kernel<<<(3 * NKC * 4096 + 255) / 256, 256>>>(proj_w);
    proj_mma_kernel<<<dim3(392, 3, NB), 256, PJ_SMEM>>>(s16, guid, proj_b, (float*)d_out);
}

// round 10
// speedup vs baseline: 3.6288x; 1.1727x over previous
#include <cuda_runtime.h>
#include <cuda_bf16.h>
#include <cstdint>

#define NB 4
#define DIMC 384
#define CC 64
#define GC 3
#define CIN 387
#define NKC 13           /* 13 k-chunks of 32 -> K=416 */

// ---------------- scratch (device globals; no allocation allowed) ----------------
__device__ float d_s2[NB * DIMC * 28 * 28];
__device__ float d_s4[NB * DIMC * 56 * 56];
__device__ float d_s8[NB * DIMC * 112 * 112];
__device__ float d_s16[NB * DIMC * 224 * 224];
__device__ float d_gres[NB * GC * 112 * 112];
__device__ float d_comp[NB * CC * 112 * 112];
__device__ float d_maskb[NB * 36 * 112 * 112];
__device__ float d_wt[NB * 9 * 224 * 224];
// pre-packed bf16-split proj weights: 3 o-tiles x 13 k-chunks x [128m x 32k]
__device__ __align__(16) __nv_bfloat16 d_pwA1[3 * NKC * 4096];
__device__ __align__(16) __nv_bfloat16 d_pwA2[3 * NKC * 4096];
// pre-packed bf16-split comp weights: 4 stages x 13 k-chunks x [64m x 32k]
__device__ __align__(16) __nv_bfloat16 d_cwA1[4 * NKC * 2048];
__device__ __align__(16) __nv_bfloat16 d_cwA2[4 * NKC * 2048];

// ---------------- packed f32x2 helpers (Blackwell FFMA2) ----------------
__device__ __forceinline__ unsigned long long ffma2(unsigned long long a,
                                                    unsigned long long b,
                                                    unsigned long long c) {
    unsigned long long d;
    asm("fma.rn.f32x2 %0, %1, %2, %3;" : "=l"(d) : "l"(a), "l"(b), "l"(c));
    return d;
}
__device__ __forceinline__ unsigned long long pack2(float lo, float hi) {
    unsigned long long d;
    asm("mov.b64 %0, {%1, %2};" : "=l"(d) : "f"(lo), "f"(hi));
    return d;
}
__device__ __forceinline__ unsigned long long dup2(float v) {
    unsigned long long d;
    asm("mov.b64 %0, {%1, %1};" : "=l"(d) : "f"(v));
    return d;
}
__device__ __forceinline__ float lo2(unsigned long long v) {
    return __uint_as_float((unsigned)(v & 0xffffffffull));
}
__device__ __forceinline__ float hi2(unsigned long long v) {
    return __uint_as_float((unsigned)(v >> 32));
}

// ---------------- smem / async helpers ----------------
__device__ __forceinline__ unsigned smem_u32(const void* p) {
    unsigned a;
    asm("{ .reg .u64 t; cvta.to.shared.u64 t, %1; cvt.u32.u64 %0, t; }"
        : "=r"(a) : "l"(p));
    return a;
}
__device__ __forceinline__ void cpasync16(unsigned dst, const void* src) {
    asm volatile("cp.async.ca.shared.global [%0], [%1], 16;"
                 :: "r"(dst), "l"(src));
}
__device__ __forceinline__ void cp_commit() {
    asm volatile("cp.async.commit_group;");
}
template <int N>
__device__ __forceinline__ void cp_wait() {
    asm volatile("cp.async.wait_group %0;" :: "n"(N));
}

// ---------------- mma.sync helpers ----------------
__device__ __forceinline__ void ldsm_x4(uint32_t* r, uint32_t addr) {
    asm volatile("ldmatrix.sync.aligned.m8n8.x4.shared.b16 {%0,%1,%2,%3}, [%4];"
                 : "=r"(r[0]), "=r"(r[1]), "=r"(r[2]), "=r"(r[3]) : "r"(addr));
}
__device__ __forceinline__ void mma_bf16(float* d, const uint32_t* a, const uint32_t* b) {
    asm volatile(
        "mma.sync.aligned.m16n8k16.row.col.f32.bf16.bf16.f32 "
        "{%0,%1,%2,%3}, {%4,%5,%6,%7}, {%8,%9}, {%0,%1,%2,%3};"
        : "+f"(d[0]), "+f"(d[1]), "+f"(d[2]), "+f"(d[3])
        : "r"(a[0]), "r"(a[1]), "r"(a[2]), "r"(a[3]), "r"(b[0]), "r"(b[1]));
}

// split a float into bf16 hi/lo parts packed as (pair of channels) words
__device__ __forceinline__ void bf16_split(float v, uint32_t& h, uint32_t& l) {
    __nv_bfloat16 hb = __float2bfloat16(v);
    __nv_bfloat16 lb = __float2bfloat16(v - __bfloat162float(hb));
    h = (uint32_t)__bfloat16_as_ushort(hb);
    l = (uint32_t)__bfloat16_as_ushort(lb);
}

// ---------------- bilinear resize matching jax.image.resize (antialias=True) ----------------
__global__ void resize_kernel(const float* __restrict__ g, float* __restrict__ out, int h) {
    int idx = blockIdx.x * blockDim.x + threadIdx.x;
    int total = NB * GC * h * h;
    if (idx >= total) return;
    int j = idx % h;
    int t = idx / h;
    int i = t % h;
    int bc = t / h;
    float scale = (float)h / 224.0f;
    float inv = 224.0f / (float)h;
    float si = (i + 0.5f) * inv - 0.5f;
    float sj = (j + 0.5f) * inv - 0.5f;
    int i0 = max(0, (int)floorf(si - inv) + 1);
    int i1 = min(223, (int)ceilf(si + inv) - 1);
    int j0 = max(0, (int)floorf(sj - inv) + 1);
    int j1 = min(223, (int)ceilf(sj + inv) - 1);
    const float* gp = g + (size_t)bc * 224 * 224;
    float wj_sum = 0.f;
    for (int jj = j0; jj <= j1; ++jj)
        wj_sum += fmaxf(0.f, 1.f - fabsf((float)jj - sj) * scale);
    float wi_sum = 0.f, acc = 0.f;
    for (int ii = i0; ii <= i1; ++ii) {
        float wi = fmaxf(0.f, 1.f - fabsf((float)ii - si) * scale);
        wi_sum += wi;
        if (wi > 0.f) {
            float row = 0.f;
            const float* rp = gp + ii * 224;
            for (int jj = j0; jj <= j1; ++jj) {
                float wj = fmaxf(0.f, 1.f - fabsf((float)jj - sj) * scale);
                row += wj * rp[jj];
            }
            acc += wi * row;
        }
    }
    out[idx] = acc / (wi_sum * wj_sum);
}

// ---------------- pack comp weights into bf16-split [m][k] tiles (per stage) ----------------
__global__ void packcw_kernel(const float* __restrict__ cw, int stage) {
    int idx = blockIdx.x * blockDim.x + threadIdx.x;
    if (idx >= NKC * 2048) return;
    int k = idx & 31;
    int m = (idx >> 5) & 63;
    int kc = idx >> 11;
    int c = kc * 32 + k;
    float w = (c < CIN) ? cw[(size_t)m * CIN + c] : 0.f;
    __nv_bfloat16 a1 = __float2bfloat16(w);
    __nv_bfloat16 a2 = __float2bfloat16(w - __bfloat162float(a1));
    int off = (stage * NKC + kc) * 2048 + m * 32 + k;
    d_cwA1[off] = a1;
    d_cwA2[off] = a2;
}

// ---------------- comp: 1x1 conv 387 -> 64 as bf16-split mma GEMM ----------------
// BM=64, BN=128 px, BK=32, K=416. Smem: A1(5120) A2(5120) B1(10240) B2(10240) = 30720/stage.
#define ROWB 80
#define CSTAGE 30720
#define CSMEM (2 * CSTAGE)
__global__ __launch_bounds__(256, 2) void comp_mma_kernel(const float* __restrict__ src,
                                                          const float* __restrict__ gres,
                                                          const float* __restrict__ cb,
                                                          float* __restrict__ comp,
                                                          int hw, int stage) {
    extern __shared__ char smem[];
    const uint32_t sb = smem_u32(smem);
    const int tid = threadIdx.x;
    const int wid = tid >> 5, lane = tid & 31;
    const int wm = wid >> 2, wn = wid & 3;          // warp grid 2 x 4 (M 32 each, N 32)
    const int b = blockIdx.y;
    const int p0 = blockIdx.x * 128;

    float acc[2][4][4];
#pragma unroll
    for (int mf = 0; mf < 2; ++mf)
#pragma unroll
        for (int nf = 0; nf < 4; ++nf)
#pragma unroll
            for (int r = 0; r < 4; ++r) acc[mf][nf][r] = 0.f;

    // B fill: channel quad cq (4 ch), pixel group pg (4 px)
    const int cq = tid & 7, pg = tid >> 3;
    const int c0l = 4 * cq, px0 = pg * 4;

    const int a_row_l = lane & 15;
    const int a_kadd = (lane >> 4) << 4;
    const int b_row_l = (lane & 7) | ((lane & 16) >> 1);
    const int b_kadd = (lane & 8) << 1;

    auto chanp = [&](int c) -> const float* {
        if (c < DIMC) return src + ((size_t)b * DIMC + c) * hw + p0;
        if (c < CIN) return gres + ((size_t)b * GC + (c - DIMC)) * hw + p0;
        return (const float*)0;
    };

    auto a_issue = [&](int kc, int s) {
        const __nv_bfloat16* g1 = d_cwA1 + (size_t)(stage * NKC + kc) * 2048;
        const __nv_bfloat16* g2 = d_cwA2 + (size_t)(stage * NKC + kc) * 2048;
        uint32_t d1 = sb + s * CSTAGE;
        uint32_t d2 = d1 + 5120;
        int row = tid >> 2, sg = tid & 3;    // 256 segs per tile
        cpasync16(d1 + row * ROWB + sg * 16, g1 + row * 32 + sg * 8);
        cpasync16(d2 + row * ROWB + sg * 16, g2 + row * 32 + sg * 8);
        cp_commit();
    };
    float4 bq[4];
    auto b_issue = [&](int kc) {
        float4 z = make_float4(0.f, 0.f, 0.f, 0.f);
        bool inb = (p0 + px0) < hw;
#pragma unroll
        for (int u = 0; u < 4; ++u) {
            const float* r = chanp(kc * 32 + c0l + u);
            bq[u] = (r && inb) ? __ldg((const float4*)(r + px0)) : z;
        }
    };
    auto b_store = [&](int s) {
        uint32_t b1 = sb + s * CSTAGE + 10240;
        uint32_t b2 = b1 + 10240;
#pragma unroll
        for (int i = 0; i < 4; ++i) {
            uint32_t h[4], l[4];
#pragma unroll
            for (int u = 0; u < 4; ++u)
                bf16_split(((const float*)&bq[u])[i], h[u], l[u]);
            uint32_t hp0 = h[0] | (h[1] << 16), hp1 = h[2] | (h[3] << 16);
            uint32_t lp0 = l[0] | (l[1] << 16), lp1 = l[2] | (l[3] << 16);
            uint32_t off = (uint32_t)(px0 + i) * ROWB + c0l * 2;
            asm volatile("st.shared.v2.b32 [%0], {%1, %2};"
                         :: "r"(b1 + off), "r"(hp0), "r"(hp1) : "memory");
            asm volatile("st.shared.v2.b32 [%0], {%1, %2};"
                         :: "r"(b2 + off), "r"(lp0), "r"(lp1) : "memory");
        }
    };

    a_issue(0, 0);
    b_issue(0);
    b_store(0);
    cp_wait<0>();
    __syncthreads();

    for (int kc = 0; kc < NKC; ++kc) {
        int s = kc & 1;
        if (kc + 1 < NKC) {
            a_issue(kc + 1, s ^ 1);
            b_issue(kc + 1);
        }
        uint32_t A1b = sb + s * CSTAGE;
        uint32_t A2b = A1b + 5120;
        uint32_t B1b = A1b + 10240;
        uint32_t B2b = A1b + 20480;
#pragma unroll
        for (int ks = 0; ks < 2; ++ks) {
            uint32_t koff = ks * 32;
            uint32_t aoff = (uint32_t)(wm * 32 + a_row_l) * ROWB + koff + a_kadd;
            uint32_t boff0 = (uint32_t)(wn * 32 + b_row_l) * ROWB + koff + b_kadd;
            uint32_t boff1 = boff0 + 16 * ROWB;
            uint32_t av[8], bv1[8], bv2[8];
            ldsm_x4(bv1, B1b + boff0);
            ldsm_x4(bv1 + 4, B1b + boff1);
#pragma unroll
            for (int mf = 0; mf < 2; ++mf)
                ldsm_x4(av + mf * 4, A1b + aoff + mf * 16 * ROWB);
#pragma unroll
            for (int mf = 0; mf < 2; ++mf)
#pragma unroll
                for (int nf = 0; nf < 4; ++nf)
                    mma_bf16(acc[mf][nf], av + mf * 4, bv1 + nf * 2);
            ldsm_x4(bv2, B2b + boff0);
            ldsm_x4(bv2 + 4, B2b + boff1);
#pragma unroll
            for (int mf = 0; mf < 2; ++mf)
#pragma unroll
                for (int nf = 0; nf < 4; ++nf)
                    mma_bf16(acc[mf][nf], av + mf * 4, bv2 + nf * 2);
#pragma unroll
            for (int mf = 0; mf < 2; ++mf)
                ldsm_x4(av + mf * 4, A2b + aoff + mf * 16 * ROWB);
#pragma unroll
            for (int mf = 0; mf < 2; ++mf)
#pragma unroll
                for (int nf = 0; nf < 4; ++nf)
                    mma_bf16(acc[mf][nf], av + mf * 4, bv1 + nf * 2);
        }
        if (kc + 1 < NKC) {
            b_store(s ^ 1);
            cp_wait<0>();
        }
        __syncthreads();
    }

#pragma unroll
    for (int mf = 0; mf < 2; ++mf) {
        int row0 = wm * 32 + mf * 16 + (lane >> 2);
        int row1 = row0 + 8;
        float bias0 = __ldg(&cb[row0]);
        float bias1 = __ldg(&cb[row1]);
        float* ob0 = comp + ((size_t)b * CC + row0) * hw;
        float* ob1 = comp + ((size_t)b * CC + row1) * hw;
        int colb = wn * 32 + (lane & 3) * 2;
#pragma unroll
        for (int nf = 0; nf < 4; ++nf) {
            int col = p0 + colb + nf * 8;
            if (col < hw) {
                *(float2*)(ob0 + col) = make_float2(acc[mf][nf][0] + bias0,
                                                    acc[mf][nf][1] + bias0);
                *(float2*)(ob1 + col) = make_float2(acc[mf][nf][2] + bias1,
                                                    acc[mf][nf][3] + bias1);
            }
        }
    }
}

// ---------------- mask: 3x3 conv 64 -> 36, pad 1 ----------------
__global__ __launch_bounds__(256) void mask_kernel(const float* __restrict__ comp,
                                                   const float* __restrict__ ew,
                                                   const float* __restrict__ eb,
                                                   float* __restrict__ maskb, int h) {
    extern __shared__ float sE[]; // [CC][9][36]
    int tid = threadIdx.x;
    for (int i = tid; i < CC * 9 * 36; i += 256) {
        int m = i % 36;
        int ck = i / 36;
        int k = ck % 9;
        int c = ck / 9;
        sE[i] = ew[(m * CC + c) * 9 + k];
    }
    __syncthreads();
    int hw = h * h;
    int pix = blockIdx.x * 256 + tid;
    int b = blockIdx.y;
    if (pix >= hw) return;
    int i = pix / h, j = pix % h;

    unsigned long long acc[18];
#pragma unroll
    for (int p = 0; p < 18; ++p)
        acc[p] = pack2(__ldg(&eb[2 * p]), __ldg(&eb[2 * p + 1]));

    int offs[9];
    bool val[9];
#pragma unroll
    for (int k = 0; k < 9; ++k) {
        int di = k / 3 - 1, dj = k % 3 - 1;
        int ii = i + di, jj = j + dj;
        val[k] = (ii >= 0) && (ii < h) && (jj >= 0) && (jj < h);
        offs[k] = val[k] ? (ii * h + jj) : 0;
    }
    const float* cp = comp + (size_t)b * CC * hw;
#pragma unroll 1
    for (int c0 = 0; c0 < CC; c0 += 2) {
        const float* cpa = cp + (size_t)c0 * hw;
        const float* cpb = cpa + hw;
        float va[9], vb[9];
#pragma unroll
        for (int k = 0; k < 9; ++k) {
            va[k] = val[k] ? cpa[offs[k]] : 0.f;
            vb[k] = val[k] ? cpb[offs[k]] : 0.f;
        }
#pragma unroll
        for (int k = 0; k < 9; ++k) {
            unsigned long long vv = dup2(va[k]);
            const ulonglong2* w2 = (const ulonglong2*)&sE[(c0 * 9 + k) * 36];
#pragma unroll
            for (int q = 0; q < 9; ++q) {
                ulonglong2 w = w2[q];
                acc[2 * q] = ffma2(vv, w.x, acc[2 * q]);
                acc[2 * q + 1] = ffma2(vv, w.y, acc[2 * q + 1]);
            }
        }
#pragma unroll
        for (int k = 0; k < 9; ++k) {
            unsigned long long vv = dup2(vb[k]);
            const ulonglong2* w2 = (const ulonglong2*)&sE[((c0 + 1) * 9 + k) * 36];
#pragma unroll
            for (int q = 0; q < 9; ++q) {
                ulonglong2 w = w2[q];
                acc[2 * q] = ffma2(vv, w.x, acc[2 * q]);
                acc[2 * q + 1] = ffma2(vv, w.y, acc[2 * q + 1]);
            }
        }
    }
    float* mp = maskb + (size_t)b * 36 * hw + pix;
#pragma unroll
    for (int p = 0; p < 18; ++p) {
        mp[(size_t)(2 * p) * hw] = lo2(acc[p]);
        mp[(size_t)(2 * p + 1) * hw] = hi2(acc[p]);
    }
}

// ---------------- pixel-shuffle + softmax: quad-contiguous weight layout ----------------
__global__ void softmax_shuffle_kernel(const float* __restrict__ maskb,
                                       float* __restrict__ wt, int h) {
    int H = 2 * h;
    int HW = H * H, hw = h * h;
    int idx = blockIdx.x * blockDim.x + threadIdx.x;
    if (idx >= NB * HW) return;
    int J = idx % H;
    int t = idx / H;
    int I = t % H;
    int b = t / H;
    int i = I >> 1, p = I & 1, j = J >> 1, q = J & 1;
    const float* mp = maskb + ((size_t)b * 36 + (p * 2 + q)) * hw + i * h + j;
    float m[9], mx = -1e30f;
#pragma unroll
    for (int k = 0; k < 9; ++k) {
        m[k] = mp[(size_t)(k * 4) * hw];
        mx = fmaxf(mx, m[k]);
    }
    float s = 0.f;
#pragma unroll
    for (int k = 0; k < 9; ++k) {
        m[k] = __expf(m[k] - mx);
        s += m[k];
    }
    float inv = 1.f / s;
    float* wp = wt + (((size_t)b * 9) * hw + i * h + j) * 4 + (p * 2 + q);
#pragma unroll
    for (int k = 0; k < 9; ++k) wp[(size_t)k * hw * 4] = m[k] * inv;
}

// ---------------- CARAFE reassembly: one thread per low-res pixel = 2x2 hi-res quad ----------------
#define CARAFE_CH 8
#define CARAFE_NE (CARAFE_CH * 324)  // 18x18 window per channel
__global__ __launch_bounds__(256) void carafe_kernel(const float* __restrict__ src,
                                                     const float* __restrict__ wt,
                                                     float* __restrict__ out, int h) {
    int H = 2 * h, hw = h * h, HW = H * H;
    int b = blockIdx.z;
    int i0 = blockIdx.y * 16;
    int j0 = blockIdx.x * 16;
    int tid = threadIdx.x;
    int ti = tid >> 4, tj = tid & 15;
    int i = i0 + ti, j = j0 + tj;
    bool valid = (i < h) && (j < h);
    __shared__ float xs[CARAFE_CH][18][18];

    float4 w4[9];
    {
        const float4* wb = (const float4*)(wt + (((size_t)b * 9) * hw + i * h + j) * 4);
#pragma unroll
        for (int k = 0; k < 9; ++k)
            w4[k] = valid ? wb[(size_t)k * hw] : make_float4(0.f, 0.f, 0.f, 0.f);
    }

    int loff[11], sflat[11];
    bool vld[11];
    int cnt = 0;
    for (int e = tid; e < CARAFE_NE; e += 256) {
        int c = e / 324;
        int r = e % 324;
        int ii = r / 18, jj = r % 18;
        int gi = i0 - 1 + ii, gj = j0 - 1 + jj;
        bool v = (gi >= 0) && (gi < h) && (gj >= 0) && (gj < h);
        loff[cnt] = c * hw + (v ? (gi * h + gj) : 0);
        sflat[cnt] = e;
        vld[cnt] = v;
        cnt++;
    }
    const float* sb = src + (size_t)b * DIMC * hw;
    float* ob = out + (size_t)b * DIMC * HW;
    float rv[11];
#pragma unroll
    for (int q = 0; q < 11; ++q)
        rv[q] = (q < cnt && vld[q]) ? __ldg(sb + loff[q]) : 0.f;

    float* xsf = &xs[0][0][0];
    int I = 2 * i, J = 2 * j;
    for (int cc = 0; cc < DIMC; cc += CARAFE_CH) {
        __syncthreads();
#pragma unroll
        for (int q = 0; q < 11; ++q)
            if (q < cnt) xsf[sflat[q]] = rv[q];
        __syncthreads();
        if (cc + CARAFE_CH < DIMC) {
            const float* sbc = sb + (size_t)(cc + CARAFE_CH) * hw;
#pragma unroll
            for (int q = 0; q < 11; ++q)
                rv[q] = (q < cnt && vld[q]) ? __ldg(sbc + loff[q]) : 0.f;
        }
#pragma unroll
        for (int c = 0; c < CARAFE_CH; ++c) {
            float a00 = 0.f, a01 = 0.f, a10 = 0.f, a11 = 0.f;
#pragma unroll
            for (int k = 0; k < 9; ++k) {
                float x = xs[c][ti + k / 3][tj + k % 3];
                a00 += w4[k].x * x;
                a01 += w4[k].y * x;
                a10 += w4[k].z * x;
                a11 += w4[k].w * x;
            }
            if (valid) {
                float* o0 = ob + (size_t)(cc + c) * HW + (size_t)I * H + J;
                *(float2*)o0 = make_float2(a00, a01);
                *(float2*)(o0 + H) = make_float2(a10, a11);
            }
        }
    }
}

// ---------------- pack proj weights into bf16-split [m][k] MMA tiles ----------------
__global__ void packw_kernel(const float* __restrict__ pw) {
    int idx = blockIdx.x * blockDim.x + threadIdx.x;
    if (idx >= 3 * NKC * 4096) return;
    int k = idx & 31;
    int m = (idx >> 5) & 127;
    int kt = idx >> 12;            // o*NKC + kc
    int o = kt / NKC, kc = kt % NKC;
    int c = kc * 32 + k;
    float w = (c < CIN) ? pw[(size_t)(o * 128 + m) * CIN + c] : 0.f;
    __nv_bfloat16 a1 = __float2bfloat16(w);
    __nv_bfloat16 a2 = __float2bfloat16(w - __bfloat162float(a1));
    int off = kt * 4096 + m * 32 + k;
    d_pwA1[off] = a1;
    d_pwA2[off] = a2;
}

// ---------------- final 1x1 conv: mma.sync bf16-split (3-term) GEMM ----------------
// BM=128 (out ch), BN=128 (px), BK=32, K=416. Smem rows [m|n][k], 40 bf16 (80B) stride.
#define STAGE_SZ 40960
#define PJ_SMEM (2 * STAGE_SZ)
__global__ __launch_bounds__(256, 2) void proj_mma_kernel(const float* __restrict__ s16,
                                                          const float* __restrict__ guid,
                                                          const float* __restrict__ pb,
                                                          float* __restrict__ out) {
    extern __shared__ char smem[];
    const uint32_t sb = smem_u32(smem);
    const int tid = threadIdx.x;
    const int wid = tid >> 5, lane = tid & 31;
    const int wm = wid >> 2, wn = wid & 3;          // warp grid 2 x 4
    const int pt = blockIdx.x, ot = blockIdx.y, b = blockIdx.z;
    const size_t NPIX = 50176;
    const size_t p0 = (size_t)pt * 128;
    const int o0 = ot * 128;

    float acc[4][4][4];
#pragma unroll
    for (int mf = 0; mf < 4; ++mf)
#pragma unroll
        for (int nf = 0; nf < 4; ++nf)
#pragma unroll
            for (int r = 0; r < 4; ++r) acc[mf][nf][r] = 0.f;

    // B fill: channel quad cq (4 ch), pixel group pg (4 px)
    const int cq = tid & 7, pg = tid >> 3;
    const int c0l = 4 * cq, px0 = pg * 4;

    const int a_row_l = lane & 15;
    const int a_kadd = (lane >> 4) << 4;
    const int b_row_l = (lane & 7) | ((lane & 16) >> 1);
    const int b_kadd = (lane & 8) << 1;

    auto chanp = [&](int c) -> const float* {
        if (c < DIMC) return s16 + ((size_t)(b * DIMC + c)) * NPIX + p0;
        if (c < CIN) return guid + ((size_t)(b * GC + (c - DIMC))) * NPIX + p0;
        return (const float*)0;
    };

    auto a_issue = [&](int kc, int s) {
        const __nv_bfloat16* g1 = d_pwA1 + (ot * NKC + kc) * 4096;
        const __nv_bfloat16* g2 = d_pwA2 + (ot * NKC + kc) * 4096;
        uint32_t d1 = sb + s * STAGE_SZ;
        uint32_t d2 = d1 + 10240;
#pragma unroll
        for (int r = 0; r < 2; ++r) {
            int seg = tid + r * 256;           // 512 segments of 16B
            int row = seg >> 2, sg = seg & 3;
            cpasync16(d1 + row * ROWB + sg * 16, g1 + row * 32 + sg * 8);
            cpasync16(d2 + row * ROWB + sg * 16, g2 + row * 32 + sg * 8);
        }
        cp_commit();
    };
    float4 bq[4];
    auto b_issue = [&](int kc) {
        float4 z = make_float4(0.f, 0.f, 0.f, 0.f);
#pragma unroll
        for (int u = 0; u < 4; ++u) {
            const float* r = chanp(kc * 32 + c0l + u);
            bq[u] = r ? __ldg((const float4*)(r + px0)) : z;
        }
    };
    auto b_store = [&](int s) {
        uint32_t b1 = sb + s * STAGE_SZ + 20480;
        uint32_t b2 = b1 + 10240;
#pragma unroll
        for (int i = 0; i < 4; ++i) {
            uint32_t h[4], l[4];
#pragma unroll
            for (int u = 0; u < 4; ++u)
                bf16_split(((const float*)&bq[u])[i], h[u], l[u]);
            uint32_t hp0 = h[0] | (h[1] << 16), hp1 = h[2] | (h[3] << 16);
            uint32_t lp0 = l[0] | (l[1] << 16), lp1 = l[2] | (l[3] << 16);
            uint32_t off = (uint32_t)(px0 + i) * ROWB + c0l * 2;
            asm volatile("st.shared.v2.b32 [%0], {%1, %2};"
                         :: "r"(b1 + off), "r"(hp0), "r"(hp1) : "memory");
            asm volatile("st.shared.v2.b32 [%0], {%1, %2};"
                         :: "r"(b2 + off), "r"(lp0), "r"(lp1) : "memory");
        }
    };

    // prefill chunk 0
    a_issue(0, 0);
    b_issue(0);
    b_store(0);
    cp_wait<0>();
    __syncthreads();

    for (int kc = 0; kc < NKC; ++kc) {
        int s = kc & 1;
        if (kc + 1 < NKC) {
            a_issue(kc + 1, s ^ 1);   // async
            b_issue(kc + 1);          // LDGs in flight during compute
        }
        uint32_t A1b = sb + s * STAGE_SZ;
        uint32_t A2b = A1b + 10240;
        uint32_t B1b = A1b + 20480;
        uint32_t B2b = A1b + 30720;
#pragma unroll
        for (int ks = 0; ks < 2; ++ks) {
            uint32_t koff = ks * 32;
            uint32_t aoff = (uint32_t)(wm * 64 + a_row_l) * ROWB + koff + a_kadd;
            uint32_t boff0 = (uint32_t)(wn * 32 + b_row_l) * ROWB + koff + b_kadd;
            uint32_t boff1 = boff0 + 16 * ROWB;
            uint32_t av[16], bv1[8], bv2[8];
            ldsm_x4(bv1, B1b + boff0);
            ldsm_x4(bv1 + 4, B1b + boff1);
#pragma unroll
            for (int mf = 0; mf < 4; ++mf)
                ldsm_x4(av + mf * 4, A1b + aoff + mf * 16 * ROWB);
#pragma unroll
            for (int mf = 0; mf < 4; ++mf)
#pragma unroll
                for (int nf = 0; nf < 4; ++nf)
                    mma_bf16(acc[mf][nf], av + mf * 4, bv1 + nf * 2);
            ldsm_x4(bv2, B2b + boff0);
            ldsm_x4(bv2 + 4, B2b + boff1);
#pragma unroll
            for (int mf = 0; mf < 4; ++mf)
#pragma unroll
                for (int nf = 0; nf < 4; ++nf)
                    mma_bf16(acc[mf][nf], av + mf * 4, bv2 + nf * 2);
#pragma unroll
            for (int mf = 0; mf < 4; ++mf)
                ldsm_x4(av + mf * 4, A2b + aoff + mf * 16 * ROWB);
#pragma unroll
            for (int mf = 0; mf < 4; ++mf)
#pragma unroll
                for (int nf = 0; nf < 4; ++nf)
                    mma_bf16(acc[mf][nf], av + mf * 4, bv1 + nf * 2);
        }
        if (kc + 1 < NKC) {
            b_store(s ^ 1);
            cp_wait<0>();
        }
        __syncthreads();
    }

    // ---- epilogue ----
#pragma unroll
    for (int mf = 0; mf < 4; ++mf) {
        int row0 = o0 + wm * 64 + mf * 16 + (lane >> 2);
        int row1 = row0 + 8;
        float bias0 = __ldg(&pb[row0]);
        float bias1 = __ldg(&pb[row1]);
        float* ob0 = out + ((size_t)(b * DIMC + row0)) * NPIX + p0 + wn * 32 + (lane & 3) * 2;
        float* ob1 = out + ((size_t)(b * DIMC + row1)) * NPIX + p0 + wn * 32 + (lane & 3) * 2;
#pragma unroll
        for (int nf = 0; nf < 4; ++nf) {
            *(float2*)(ob0 + nf * 8) = make_float2(acc[mf][nf][0] + bias0,
                                                   acc[mf][nf][1] + bias0);
            *(float2*)(ob1 + nf * 8) = make_float2(acc[mf][nf][2] + bias1,
                                                   acc[mf][nf][3] + bias1);
        }
    }
}

// ---------------- driver ----------------
extern "C" void kernel_launch(void* const* d_in, const int* in_sizes, int n_in,
                              void* d_out, int out_size) {
    (void)in_sizes; (void)n_in; (void)out_size;
    const float* source = (const float*)d_in[0];
    const float* guid = (const float*)d_in[1];
    const float* proj_w = (const float*)d_in[18];
    const float* proj_b = (const float*)d_in[19];

    float *s2, *s4, *s8, *s16, *gres, *comp, *maskb, *wtb;
    cudaGetSymbolAddress((void**)&s2, d_s2);
    cudaGetSymbolAddress((void**)&s4, d_s4);
    cudaGetSymbolAddress((void**)&s8, d_s8);
    cudaGetSymbolAddress((void**)&s16, d_s16);
    cudaGetSymbolAddress((void**)&gres, d_gres);
    cudaGetSymbolAddress((void**)&comp, d_comp);
    cudaGetSymbolAddress((void**)&maskb, d_maskb);
    cudaGetSymbolAddress((void**)&wtb, d_wt);

    cudaFuncSetAttribute(mask_kernel, cudaFuncAttributeMaxDynamicSharedMemorySize,
                         CC * 9 * 36 * 4);
    cudaFuncSetAttribute(comp_mma_kernel, cudaFuncAttributeMaxDynamicSharedMemorySize,
                         CSMEM);
    cudaFuncSetAttribute(proj_mma_kernel, cudaFuncAttributeMaxDynamicSharedMemorySize,
                         PJ_SMEM);

    // pack all weights upfront (independent of stage outputs)
    packw_kernel<<<(3 * NKC * 4096 + 255) / 256, 256>>>(proj_w);
    for (int s = 0; s < 4; ++s)
        packcw_kernel<<<(NKC * 2048 + 255) / 256, 256>>>((const float*)d_in[2 + 4 * s], s);

    const float* cur = source;
    float* outs[4] = {s2, s4, s8, s16};
    const int hs[4] = {14, 28, 56, 112};
    for (int s = 0; s < 4; ++s) {
        int h = hs[s], hw = h * h, H = 2 * h, HW = H * H;
        const float* cb = (const float*)d_in[3 + 4 * s];
        const float* ew = (const float*)d_in[4 + 4 * s];
        const float* eb = (const float*)d_in[5 + 4 * s];
        resize_kernel<<<(NB * GC * hw + 255) / 256, 256>>>(guid, gres, h);
        comp_mma_kernel<<<dim3((hw + 127) / 128, NB), 256, CSMEM>>>(cur, gres, cb, comp,
                                                                    hw, s);
        mask_kernel<<<dim3((hw + 255) / 256, NB), 256, CC * 9 * 36 * 4>>>(comp, ew, eb,
                                                                          maskb, h);
        softmax_shuffle_kernel<<<(NB * HW + 255) / 256, 256>>>(maskb, wtb, h);
        int nt = (h + 15) / 16;
        carafe_kernel<<<dim3(nt, nt, NB), 256>>>(cur, wtb, outs[s], h);
        cur = outs[s];
    }
    proj_mma_kernel<<<dim3(392, 3, NB), 256, PJ_SMEM>>>(s16, guid, proj_b, (float*)d_out);
}